// round 8
// baseline (speedup 1.0000x reference)
#include <cuda_runtime.h>
#include <cuda_bf16.h>
#include <cstdint>
#include <cstddef>

// T=512, B=256, NX=256, NU=256, ND=128, NM=128, NDT=128, NH=512, M=T*B=131072
static constexpr size_t X_OFF     = 0;
static constexpr size_t Y_OFF     = 33554432;
static constexpr size_t SXMIN_OFF = 33685504;
static constexpr size_t SXMAX_OFF = 67239936;
static constexpr size_t SUMIN_OFF = 100794368;
static constexpr size_t SUMAX_OFF = 134348800;

// Powers: g_P[k][j*256+i] = (A_eff)^(k+1)[j][i]
__device__ float g_P[8 * 65536];
__device__ __nv_bfloat16 g_PT_hi[8 * 65536];  // g_PT[k][n*256+kk] = P_k[kk][n]
__device__ __nv_bfloat16 g_PT_lo[8 * 65536];

__device__ __nv_bfloat16 g_h_hi[(size_t)131072 * 512];
__device__ __nv_bfloat16 g_h_lo[(size_t)131072 * 512];
__device__ __nv_bfloat16 g_u_hi[(size_t)131072 * 256];
__device__ __nv_bfloat16 g_u_lo[(size_t)131072 * 256];

static constexpr size_t CSTRIDE = (size_t)16384 * 256;  // c_j block stride in g_h region

// ---------------- scalar helpers ----------------
__device__ __forceinline__ unsigned long long pk2(float a, float b) {
    unsigned long long r;
    asm("mov.b64 %0, {%1, %2};" : "=l"(r) : "r"(__float_as_uint(a)), "r"(__float_as_uint(b)));
    return r;
}
__device__ __forceinline__ unsigned long long bcast2(float v) {
    unsigned long long r;
    unsigned u = __float_as_uint(v);
    asm("mov.b64 %0, {%1, %1};" : "=l"(r) : "r"(u));
    return r;
}
__device__ __forceinline__ void fma2(unsigned long long& d, unsigned long long a, unsigned long long b) {
    asm("fma.rn.f32x2 %0, %1, %2, %0;" : "+l"(d) : "l"(a), "l"(b));
}
__device__ __forceinline__ void add2(unsigned long long& d, unsigned long long a) {
    asm("add.rn.f32x2 %0, %0, %1;" : "+l"(d) : "l"(a));
}
__device__ __forceinline__ float2 unpk(unsigned long long v) {
    unsigned lo, hi;
    asm("mov.b64 {%0, %1}, %2;" : "=r"(lo), "=r"(hi) : "l"(v));
    return make_float2(__uint_as_float(lo), __uint_as_float(hi));
}
__device__ __forceinline__ unsigned smem_u32(const void* p) {
    unsigned r;
    asm("{ .reg .u64 t; cvta.to.shared.u64 t, %1; cvt.u32.u64 %0, t; }" : "=r"(r) : "l"(p));
    return r;
}
__device__ __forceinline__ unsigned ctarank() {
    unsigned r;
    asm("mov.u32 %0, %%cluster_ctarank;" : "=r"(r));
    return r;
}
__device__ __forceinline__ void split1(float v, __nv_bfloat16& h, __nv_bfloat16& l) {
    h = __float2bfloat16_rn(v);
    l = __float2bfloat16_rn(v - __bfloat162float(h));
}
__device__ __forceinline__ void ldsm4(unsigned* r, uint32_t addr) {
    asm volatile("ldmatrix.sync.aligned.m8n8.x4.shared.b16 {%0,%1,%2,%3}, [%4];"
                 : "=r"(r[0]), "=r"(r[1]), "=r"(r[2]), "=r"(r[3]) : "r"(addr));
}
__device__ __forceinline__ void mma_bf16(float* d, const unsigned* a, unsigned b0, unsigned b1) {
    asm volatile(
        "mma.sync.aligned.m16n8k16.row.col.f32.bf16.bf16.f32 "
        "{%0,%1,%2,%3}, {%4,%5,%6,%7}, {%8,%9}, {%0,%1,%2,%3};"
        : "+f"(d[0]), "+f"(d[1]), "+f"(d[2]), "+f"(d[3])
        : "r"(a[0]), "r"(a[1]), "r"(a[2]), "r"(a[3]), "r"(b0), "r"(b1));
}
__device__ __forceinline__ void cvt8(const float* f, uint4& hi4, uint4& lo4) {
    unsigned h[4], l[4];
#pragma unroll
    for (int i = 0; i < 4; i++) {
        __nv_bfloat16 h0, l0, h1, l1;
        split1(f[2 * i], h0, l0);
        split1(f[2 * i + 1], h1, l1);
        h[i] = (unsigned)__bfloat16_as_ushort(h0) | ((unsigned)__bfloat16_as_ushort(h1) << 16);
        l[i] = (unsigned)__bfloat16_as_ushort(l0) | ((unsigned)__bfloat16_as_ushort(l1) << 16);
    }
    hi4 = make_uint4(h[0], h[1], h[2], h[3]);
    lo4 = make_uint4(l[0], l[1], l[2], l[3]);
}
__device__ __forceinline__ void load_pair_f32(const float* src, uint4& h4, uint4& l4) {
    float f[8];
    *(float4*)f = *(const float4*)src;
    *(float4*)(f + 4) = *(const float4*)(src + 4);
    cvt8(f, h4, l4);
}
__device__ __forceinline__ unsigned pack_hilo(float a, float b, unsigned& lo_out) {
    __nv_bfloat16 h0, l0, h1, l1;
    split1(a, h0, l0);
    split1(b, h1, l1);
    lo_out = (unsigned)__bfloat16_as_ushort(l0) | ((unsigned)__bfloat16_as_ushort(l1) << 16);
    return (unsigned)__bfloat16_as_ushort(h0) | ((unsigned)__bfloat16_as_ushort(h1) << 16);
}
__device__ __forceinline__ float bf2f(__nv_bfloat16 v) { return __bfloat162float(v); }

// ---------------- A_eff prep (writes g_P[0]) ----------------
__global__ void build_aeff_kernel(const float* __restrict__ Aw, const float* __restrict__ Asc) {
    int r = blockIdx.x, c = threadIdx.x;
    __shared__ float red[256];
    float w = Aw[r * 256 + c];
    red[c] = w;
    __syncthreads();
#pragma unroll
    for (int s = 128; s > 0; s >>= 1) {
        if (c < s) red[c] = fmaxf(red[c], red[c + s]);
        __syncthreads();
    }
    float mx = red[0];
    __syncthreads();
    float e = expf(w - mx);
    red[c] = e;
    __syncthreads();
#pragma unroll
    for (int s = 128; s > 0; s >>= 1) {
        if (c < s) red[c] += red[c + s];
        __syncthreads();
    }
    float p = e / red[0];
    float sg = 1.f / (1.f + expf(-Asc[r * 256 + c]));
    g_P[c * 256 + r] = (1.f - 0.1f * sg) * p;
}

// ---------------- matrix powers ----------------
__global__ void pow_kernel(int lsrc, int rfirst, int dstfirst) {
    int row = blockIdx.x, i = threadIdx.x, z = blockIdx.z;
    const float* L = g_P + (size_t)lsrc * 65536;
    const float* R = g_P + (size_t)(rfirst + z) * 65536;
    float* Cd = g_P + (size_t)(dstfirst + z) * 65536;
    __shared__ float Lrow[256];
    Lrow[i] = L[row * 256 + i];
    __syncthreads();
    float a0 = 0, a1 = 0, a2 = 0, a3 = 0;
#pragma unroll 8
    for (int m = 0; m < 256; m += 4) {
        a0 = fmaf(Lrow[m + 0], R[(m + 0) * 256 + i], a0);
        a1 = fmaf(Lrow[m + 1], R[(m + 1) * 256 + i], a1);
        a2 = fmaf(Lrow[m + 2], R[(m + 2) * 256 + i], a2);
        a3 = fmaf(Lrow[m + 3], R[(m + 3) * 256 + i], a3);
    }
    Cd[row * 256 + i] = (a0 + a1) + (a2 + a3);
}

// ---------------- transpose+split powers ----------------
__global__ void transp_kernel() {
    int k = blockIdx.x;
    int kt = blockIdx.y * 32;
    int nt = blockIdx.z * 32;
    int tx = threadIdx.x, ty = threadIdx.y;
    __shared__ float tile[32][33];
    const float* P = g_P + (size_t)k * 65536;
#pragma unroll
    for (int r = 0; r < 4; r++) {
        int kk = kt + ty + r * 8;
        tile[ty + r * 8][tx] = P[kk * 256 + nt + tx];
    }
    __syncthreads();
#pragma unroll
    for (int r = 0; r < 4; r++) {
        int n = nt + ty + r * 8;
        float v = tile[tx][ty + r * 8];
        __nv_bfloat16 h, l;
        split1(v, h, l);
        size_t o = (size_t)k * 65536 + (size_t)n * 256 + kt + tx;
        g_PT_hi[o] = h;
        g_PT_lo[o] = l;
    }
}

// ---------------- unified pipelined HMMA GEMM ----------------
// MODE 0: A=concat(M_flow,DT) K=256, B=hf1, N=512 -> g_h hi/lo = relu
// MODE 1: A=g_h K=512, B=hf2, N=256 -> g_u hi/lo = relu, Su_min/max
// MODE 2: A=concat(g_u,D) K=384, B=concat(B_W,E_W), N=256 -> drive to out X, + c0 copy
// MODE 3: csweep: A=g_c[j-1] K=256, B=PT[0] -> c_j = C + drive_t
// MODE 4: recon:  A=g_s    K=256, B=PT[j] (j=blockIdx.z) -> X,Sx,Y epilogue
static constexpr int SROW = 144;
static constexpr uint32_t STG_STRIDE = 73728;          // 4 * 18432
static constexpr uint32_t AHI = 0, ALO = 18432, BHI = 36864, BLO = 55296;
static constexpr int GSMEM = 2 * (int)STG_STRIDE;      // 147456

template <int MODE>
__global__ void __launch_bounds__(256, 1)
gemm_mma_kernel(const float* __restrict__ pA0, const float* __restrict__ pA1,
                const float* __restrict__ pB0, const float* __restrict__ pB1,
                const float* __restrict__ p4, const float* __restrict__ p5,
                float* __restrict__ out, int jparam) {
    constexpr int K = (MODE == 0) ? 256 : (MODE == 1) ? 512 : (MODE == 2) ? 384 : 256;
    constexpr int NCH = K / 64;

    extern __shared__ char smem[];
    uint32_t sb = smem_u32(smem);

    int tid = threadIdx.x;
    int lane = tid & 31;
    int wid = tid >> 5;
    int wm = wid & 3;
    int wn = wid >> 2;
    int m0 = blockIdx.y * 128;
    int n0 = blockIdx.x * 128;
    int j = (MODE == 4) ? (int)blockIdx.z : jparam;

    const __nv_bfloat16* Ahi = nullptr;
    const __nv_bfloat16* Alo = nullptr;
    const __nv_bfloat16* Bhi = nullptr;
    const __nv_bfloat16* Blo = nullptr;
    if constexpr (MODE == 3) {
        Ahi = g_h_hi + (size_t)(j - 1) * CSTRIDE;
        Alo = g_h_lo + (size_t)(j - 1) * CSTRIDE;
        Bhi = g_PT_hi;
        Blo = g_PT_lo;
    } else if constexpr (MODE == 4) {
        Ahi = g_u_hi;
        Alo = g_u_lo;
        Bhi = g_PT_hi + (size_t)j * 65536;
        Blo = g_PT_lo + (size_t)j * 65536;
    }

    int ld_row = tid >> 3, ld_c8 = tid & 7;  // per-thread tile coords (stride 32 rows/iter)

    uint4 ra_h[4], ra_l[4], rb_h[4], rb_l[4];

    auto loadA = [&](int kc) {
        int k0 = kc * 64;
#pragma unroll
        for (int it = 0; it < 4; it++) {
            int row = ld_row + it * 32;
            int k = k0 + ld_c8 * 8;
            size_t m = (size_t)(m0 + row);
            if constexpr (MODE == 0) {
                const float* src = (k < 128) ? pA0 + m * 128 + k : pA1 + m * 128 + (k - 128);
                load_pair_f32(src, ra_h[it], ra_l[it]);
            } else if constexpr (MODE == 1) {
                size_t gi = m * 512 + k;
                ra_h[it] = *(const uint4*)(g_h_hi + gi);
                ra_l[it] = *(const uint4*)(g_h_lo + gi);
            } else if constexpr (MODE == 2) {
                if (k < 256) {
                    size_t gi = m * 256 + k;
                    ra_h[it] = *(const uint4*)(g_u_hi + gi);
                    ra_l[it] = *(const uint4*)(g_u_lo + gi);
                } else {
                    load_pair_f32(pA1 + m * 128 + (k - 256), ra_h[it], ra_l[it]);
                }
            } else {
                size_t gi = m * 256 + k;
                ra_h[it] = *(const uint4*)(Ahi + gi);
                ra_l[it] = *(const uint4*)(Alo + gi);
            }
        }
    };
    auto loadB = [&](int kc) {
        int k0 = kc * 64;
#pragma unroll
        for (int it = 0; it < 4; it++) {
            int row = ld_row + it * 32;
            int k = k0 + ld_c8 * 8;
            size_t n = (size_t)(n0 + row);
            if constexpr (MODE == 0) {
                load_pair_f32(pB0 + n * 256 + k, rb_h[it], rb_l[it]);
            } else if constexpr (MODE == 1) {
                load_pair_f32(pB0 + n * 512 + k, rb_h[it], rb_l[it]);
            } else if constexpr (MODE == 2) {
                const float* src = (k < 256) ? pB0 + n * 256 + k : pB1 + n * 128 + (k - 256);
                load_pair_f32(src, rb_h[it], rb_l[it]);
            } else {
                size_t bi = n * 256 + k;
                rb_h[it] = *(const uint4*)(Bhi + bi);
                rb_l[it] = *(const uint4*)(Blo + bi);
            }
        }
    };
    auto stsTile = [&](int stg) {
        char* base = smem + (size_t)stg * STG_STRIDE;
#pragma unroll
        for (int it = 0; it < 4; it++) {
            uint32_t off = (uint32_t)((ld_row + it * 32) * SROW + ld_c8 * 16);
            *(uint4*)(base + AHI + off) = ra_h[it];
            *(uint4*)(base + ALO + off) = ra_l[it];
            *(uint4*)(base + BHI + off) = rb_h[it];
            *(uint4*)(base + BLO + off) = rb_l[it];
        }
    };

    uint32_t a_off = (uint32_t)((lane & 15) * SROW + ((lane >> 4) << 3) * 2);
    uint32_t b_off = (uint32_t)((((lane & 7) | ((lane >> 4) << 3))) * SROW +
                                (((lane >> 3) & 1) << 3) * 2);

    float d[2][8][4];
#pragma unroll
    for (int i = 0; i < 2; i++)
#pragma unroll
        for (int jq = 0; jq < 8; jq++)
#pragma unroll
            for (int kq = 0; kq < 4; kq++) d[i][jq][kq] = 0.f;

    auto mmaChunk = [&](int stg) {
        uint32_t bs = sb + (uint32_t)stg * STG_STRIDE;
#pragma unroll
        for (int ks = 0; ks < 4; ks++) {
            unsigned ah[2][4], al[2][4];
#pragma unroll
            for (int mt = 0; mt < 2; mt++) {
                uint32_t base = bs + (uint32_t)((wm * 32 + mt * 16) * SROW + ks * 32) + a_off;
                ldsm4(ah[mt], base + AHI);
                ldsm4(al[mt], base + ALO);
            }
#pragma unroll
            for (int nt = 0; nt < 4; nt++) {
                unsigned bh[4], bl[4];
                uint32_t base = bs + (uint32_t)((wn * 64 + nt * 16) * SROW + ks * 32) + b_off;
                ldsm4(bh, base + BHI);
                ldsm4(bl, base + BLO);
#pragma unroll
                for (int mt = 0; mt < 2; mt++) {
#pragma unroll
                    for (int nn = 0; nn < 2; nn++) {
                        float* dd = d[mt][nt * 2 + nn];
                        mma_bf16(dd, ah[mt], bh[2 * nn], bh[2 * nn + 1]);
                        mma_bf16(dd, ah[mt], bl[2 * nn], bl[2 * nn + 1]);
                        mma_bf16(dd, al[mt], bh[2 * nn], bh[2 * nn + 1]);
                    }
                }
            }
        }
    };

    // pipelined mainloop
    loadA(0);
    loadB(0);
    stsTile(0);
    __syncthreads();
#pragma unroll
    for (int kc = 0; kc < NCH; kc++) {
        if (kc + 1 < NCH) {
            loadA(kc + 1);
            loadB(kc + 1);
        }
        mmaChunk(kc & 1);
        if (kc + 1 < NCH) {
            stsTile((kc + 1) & 1);
            __syncthreads();
        }
    }

    // ---- epilogue ----
    int g = lane >> 2, q = lane & 3;
#pragma unroll
    for (int mt = 0; mt < 2; mt++) {
        int r0 = m0 + wm * 32 + mt * 16 + g;
#pragma unroll
        for (int jq = 0; jq < 8; jq++) {
            int c = n0 + wn * 64 + jq * 8 + 2 * q;
            float* dd = d[mt][jq];
#pragma unroll
            for (int h = 0; h < 2; h++) {
                int m = r0 + h * 8;
                float v0 = dd[2 * h], v1 = dd[2 * h + 1];
                if constexpr (MODE == 0) {
                    float u0 = fmaxf(v0, 0.f), u1 = fmaxf(v1, 0.f);
                    size_t idx = (size_t)m * 512 + c;
                    unsigned lp, hp = pack_hilo(u0, u1, lp);
                    *(unsigned*)(g_h_hi + idx) = hp;
                    *(unsigned*)(g_h_lo + idx) = lp;
                } else if constexpr (MODE == 1) {
                    float u0 = fmaxf(v0, 0.f), u1 = fmaxf(v1, 0.f);
                    size_t idx = (size_t)m * 256 + c;
                    unsigned lp, hp = pack_hilo(u0, u1, lp);
                    *(unsigned*)(g_u_hi + idx) = hp;
                    *(unsigned*)(g_u_lo + idx) = lp;
                    float2 mn = *(const float2*)(p4 + idx);
                    float2 mx = *(const float2*)(p5 + idx);
                    *(float2*)(out + SUMIN_OFF + idx) =
                        make_float2(fmaxf(mn.x - u0, 0.f), fmaxf(mn.y - u1, 0.f));
                    *(float2*)(out + SUMAX_OFF + idx) =
                        make_float2(fmaxf(u0 - mx.x, 0.f), fmaxf(u1 - mx.y, 0.f));
                } else if constexpr (MODE == 2) {
                    size_t idx = (size_t)m * 256 + c;
                    *(float2*)(out + X_OFF + idx) = make_float2(v0, v1);
                    int trow = m >> 8;
                    if ((trow & 7) == 0) {  // fused c0 init: drive at t=8b
                        int b = trow >> 3, batch = m & 255;
                        size_t ci = ((size_t)b * 256 + batch) * 256 + c;
                        unsigned lp, hp = pack_hilo(v0, v1, lp);
                        *(unsigned*)(g_h_hi + ci) = hp;
                        *(unsigned*)(g_h_lo + ci) = lp;
                    }
                } else if constexpr (MODE == 3) {
                    int b = m >> 8, batch = m & 255;
                    int t = 8 * b + j;
                    size_t xidx = (((size_t)t * 256) + batch) * 256 + c;
                    size_t ci = (size_t)j * CSTRIDE + (size_t)m * 256 + c;
                    float2 dr = *(const float2*)(out + X_OFF + xidx);
                    float s0 = v0 + dr.x, s1 = v1 + dr.y;
                    unsigned lp, hp = pack_hilo(s0, s1, lp);
                    *(unsigned*)(g_h_hi + ci) = hp;
                    *(unsigned*)(g_h_lo + ci) = lp;
                } else {
                    int b = m >> 8, batch = m & 255;
                    int t = 8 * b + j;
                    size_t xidx = (((size_t)t * 256) + batch) * 256 + c;
                    size_t ci = (size_t)j * CSTRIDE + (size_t)m * 256 + c;
                    unsigned chp = *(const unsigned*)(g_h_hi + ci);
                    unsigned clp = *(const unsigned*)(g_h_lo + ci);
                    __nv_bfloat162 ch = *(__nv_bfloat162*)&chp;
                    __nv_bfloat162 cl = *(__nv_bfloat162*)&clp;
                    float xv0 = v0 + bf2f(__low2bfloat16(ch)) + bf2f(__low2bfloat16(cl));
                    float xv1 = v1 + bf2f(__high2bfloat16(ch)) + bf2f(__high2bfloat16(cl));
                    *(float2*)(out + X_OFF + xidx) = make_float2(xv0, xv1);
                    float2 mn = *(const float2*)(p4 + xidx);
                    float2 mx = *(const float2*)(p5 + xidx);
                    *(float2*)(out + SXMIN_OFF + xidx) =
                        make_float2(fmaxf(mn.x - xv0, 0.f), fmaxf(mn.y - xv1, 0.f));
                    *(float2*)(out + SXMAX_OFF + xidx) =
                        make_float2(fmaxf(xv0 - mx.x, 0.f), fmaxf(xv1 - mx.y, 0.f));
                    if (c == 254) out[Y_OFF + (size_t)t * 256 + batch] = xv1;
                }
            }
        }
    }
}

// ---------------- carry scan: s_{b+1} = s_b @ A^8 + c_{b,7}, 63 steps ----------------
struct ScanSmem {
    float A[256][128];
    ulonglong2 xs2[2][256];
    unsigned long long part[4][64][2][2];
};

__global__ void __launch_bounds__(256, 1) __cluster_dims__(2, 1, 1)
carry_scan_kernel(const float* __restrict__ x0) {
    extern __shared__ char smem_raw[];
    ScanSmem* S = reinterpret_cast<ScanSmem*>(smem_raw);
    int tid = threadIdx.x;
    unsigned rank = ctarank();
    int b0 = (int)(blockIdx.x >> 1) * 4;

    const float* A8 = g_P + 7 * 65536;
#pragma unroll
    for (int it = 0; it < 32; it++) {
        int idx4 = tid + it * 256;
        int jq = idx4 >> 5;
        int c4 = idx4 & 31;
        float4 v = *(const float4*)(A8 + (size_t)jq * 256 + rank * 128 + c4 * 4);
        *(float4*)(&S->A[jq][c4 * 4]) = v;
    }
    {
        int jq = tid;
        float a[4];
#pragma unroll
        for (int r = 0; r < 4; r++) {
            a[r] = x0[(b0 + r) * 256 + jq];
            __nv_bfloat16 h, l;
            split1(a[r], h, l);
            size_t si = (size_t)(b0 + r) * 256 + jq;
            g_u_hi[si] = h;
            g_u_lo[si] = l;
        }
        S->xs2[0][jq] = make_ulonglong2(pk2(a[0], a[1]), pk2(a[2], a[3]));
    }
    __syncthreads();

    const int jj = tid >> 6;
    const int cp = tid & 63;
    const int il = tid & 127;
    const int h  = tid >> 7;
    const int gcol = (int)rank * 128 + il;

    const __nv_bfloat16* c7h = g_h_hi + (size_t)7 * CSTRIDE;
    const __nv_bfloat16* c7l = g_h_lo + (size_t)7 * CSTRIDE;

    float pf_d0, pf_d1;
    {
        size_t ci = ((size_t)(b0 + 2 * h)) * 256 + gcol;
        pf_d0 = bf2f(c7h[ci]) + bf2f(c7l[ci]);
        pf_d1 = bf2f(c7h[ci + 256]) + bf2f(c7l[ci + 256]);
    }

    for (int b = 0; b < 63; b++) {
        int p = b & 1;
        unsigned long long a00 = 0, a01 = 0, a10 = 0, a11 = 0;
        const ulonglong2* xb = S->xs2[p];
        const float2* Arow = (const float2*)&S->A[jj * 64][0] + cp;
#pragma unroll 8
        for (int it = 0; it < 64; it++) {
            int jq = jj * 64 + it;
            float2 a = Arow[(size_t)it * 64];
            ulonglong2 xv = xb[jq];
            unsigned long long b0p = bcast2(a.x), b1p = bcast2(a.y);
            fma2(a00, b0p, xv.x);
            fma2(a01, b0p, xv.y);
            fma2(a10, b1p, xv.x);
            fma2(a11, b1p, xv.y);
        }
        S->part[jj][cp][0][0] = a00;
        S->part[jj][cp][0][1] = a01;
        S->part[jj][cp][1][0] = a10;
        S->part[jj][cp][1][1] = a11;
        __syncthreads();

        int cp2 = il >> 1, cip = il & 1;
        unsigned long long s = S->part[0][cp2][cip][h];
        add2(s, S->part[1][cp2][cip][h]);
        add2(s, S->part[2][cp2][cip][h]);
        add2(s, S->part[3][cp2][cip][h]);
        float2 sv = unpk(s);
        float v0 = sv.x + pf_d0;
        float v1 = sv.y + pf_d1;

        {
            size_t row0 = (size_t)(b + 1) * 256 + b0 + 2 * h;
            __nv_bfloat16 hh, ll;
            split1(v0, hh, ll);
            g_u_hi[row0 * 256 + gcol] = hh;
            g_u_lo[row0 * 256 + gcol] = ll;
            split1(v1, hh, ll);
            g_u_hi[(row0 + 1) * 256 + gcol] = hh;
            g_u_lo[(row0 + 1) * 256 + gcol] = ll;
        }

        unsigned long long xn = pk2(v0, v1);
        unsigned long long* dst =
            (h == 0) ? &S->xs2[p ^ 1][gcol].x : &S->xs2[p ^ 1][gcol].y;
        *dst = xn;
        unsigned laddr = smem_u32(dst);
        unsigned raddr;
        asm("mapa.shared::cluster.u32 %0, %1, %2;" : "=r"(raddr) : "r"(laddr), "r"(rank ^ 1u));
        asm volatile("st.shared::cluster.u64 [%0], %1;" :: "r"(raddr), "l"(xn) : "memory");

        int bn = (b < 62) ? b + 1 : 62;
        size_t cin = ((size_t)bn * 256 + b0 + 2 * h) * 256 + gcol;
        pf_d0 = bf2f(c7h[cin]) + bf2f(c7l[cin]);
        pf_d1 = bf2f(c7h[cin + 256]) + bf2f(c7l[cin + 256]);

        asm volatile("barrier.cluster.arrive.aligned;" ::: "memory");
        asm volatile("barrier.cluster.wait.aligned;" ::: "memory");
    }
}

// ---------------- launch ----------------
extern "C" void kernel_launch(void* const* d_in, const int* in_sizes, int n_in,
                              void* d_out, int out_size) {
    const float* x      = (const float*)d_in[0];
    const float* M_flow = (const float*)d_in[1];
    const float* DT     = (const float*)d_in[2];
    const float* D      = (const float*)d_in[3];
    const float* XMIN   = (const float*)d_in[4];
    const float* XMAX   = (const float*)d_in[5];
    const float* UMIN   = (const float*)d_in[6];
    const float* UMAX   = (const float*)d_in[7];
    const float* A_w    = (const float*)d_in[8];
    const float* A_sc   = (const float*)d_in[9];
    const float* B_W    = (const float*)d_in[10];
    const float* E_W    = (const float*)d_in[11];
    const float* hf1_W  = (const float*)d_in[12];
    const float* hf2_W  = (const float*)d_in[13];
    float* out = (float*)d_out;

    build_aeff_kernel<<<256, 256>>>(A_w, A_sc);
    pow_kernel<<<dim3(256, 1, 1), 256>>>(0, 0, 1);
    pow_kernel<<<dim3(256, 1, 2), 256>>>(1, 0, 2);
    pow_kernel<<<dim3(256, 1, 4), 256>>>(3, 0, 4);
    transp_kernel<<<dim3(8, 8, 8), dim3(32, 8)>>>();

    cudaFuncSetAttribute(gemm_mma_kernel<0>, cudaFuncAttributeMaxDynamicSharedMemorySize, GSMEM);
    cudaFuncSetAttribute(gemm_mma_kernel<1>, cudaFuncAttributeMaxDynamicSharedMemorySize, GSMEM);
    cudaFuncSetAttribute(gemm_mma_kernel<2>, cudaFuncAttributeMaxDynamicSharedMemorySize, GSMEM);
    cudaFuncSetAttribute(gemm_mma_kernel<3>, cudaFuncAttributeMaxDynamicSharedMemorySize, GSMEM);
    cudaFuncSetAttribute(gemm_mma_kernel<4>, cudaFuncAttributeMaxDynamicSharedMemorySize, GSMEM);

    gemm_mma_kernel<0><<<dim3(4, 1024), 256, GSMEM>>>(M_flow, DT, hf1_W, nullptr, nullptr, nullptr, out, 0);
    gemm_mma_kernel<1><<<dim3(2, 1024), 256, GSMEM>>>(nullptr, nullptr, hf2_W, nullptr, UMIN, UMAX, out, 0);
    gemm_mma_kernel<2><<<dim3(2, 1024), 256, GSMEM>>>(nullptr, D, B_W, E_W, nullptr, nullptr, out, 0);

    for (int j = 1; j <= 7; j++)
        gemm_mma_kernel<3><<<dim3(2, 128), 256, GSMEM>>>(nullptr, nullptr, nullptr, nullptr, nullptr, nullptr, out, j);

    cudaFuncSetAttribute(carry_scan_kernel, cudaFuncAttributeMaxDynamicSharedMemorySize,
                         (int)sizeof(ScanSmem));
    carry_scan_kernel<<<128, 256, sizeof(ScanSmem)>>>(x);

    gemm_mma_kernel<4><<<dim3(2, 128, 8), 256, GSMEM>>>(nullptr, nullptr, nullptr, nullptr, XMIN, XMAX, out, 0);
}

// round 9
// speedup vs baseline: 1.0937x; 1.0937x over previous
#include <cuda_runtime.h>
#include <cuda_bf16.h>
#include <cstdint>
#include <cstddef>

// T=512, B=256, NX=256, NU=256, ND=128, NM=128, NDT=128, NH=512, M=T*B=131072
static constexpr size_t X_OFF     = 0;
static constexpr size_t Y_OFF     = 33554432;
static constexpr size_t SXMIN_OFF = 33685504;
static constexpr size_t SXMAX_OFF = 67239936;
static constexpr size_t SUMIN_OFF = 100794368;
static constexpr size_t SUMAX_OFF = 134348800;

// Powers: g_P[k][j*256+i] = (A_eff)^(k+1)[j][i]
__device__ float g_P[8 * 65536];
__device__ __nv_bfloat16 g_PT_hi[8 * 65536];  // g_PT[k][n*256+kk] = P_k[kk][n]
__device__ __nv_bfloat16 g_PT_lo[8 * 65536];

__device__ __nv_bfloat16 g_h_hi[(size_t)131072 * 512];
__device__ __nv_bfloat16 g_h_lo[(size_t)131072 * 512];
__device__ __nv_bfloat16 g_u_hi[(size_t)131072 * 256];
__device__ __nv_bfloat16 g_u_lo[(size_t)131072 * 256];

// pre-split fp32 operands (hi/lo bf16)
__device__ __nv_bfloat16 g_mu_hi[(size_t)131072 * 256];
__device__ __nv_bfloat16 g_mu_lo[(size_t)131072 * 256];
__device__ __nv_bfloat16 g_D_hi[(size_t)131072 * 128];
__device__ __nv_bfloat16 g_D_lo[(size_t)131072 * 128];
__device__ __nv_bfloat16 g_w1_hi[512 * 256];
__device__ __nv_bfloat16 g_w1_lo[512 * 256];
__device__ __nv_bfloat16 g_w2_hi[256 * 512];
__device__ __nv_bfloat16 g_w2_lo[256 * 512];
__device__ __nv_bfloat16 g_be_hi[256 * 384];
__device__ __nv_bfloat16 g_be_lo[256 * 384];

static constexpr size_t CSTRIDE = (size_t)16384 * 256;  // c_j block stride in g_h region

// ---------------- scalar helpers ----------------
__device__ __forceinline__ unsigned long long pk2(float a, float b) {
    unsigned long long r;
    asm("mov.b64 %0, {%1, %2};" : "=l"(r) : "r"(__float_as_uint(a)), "r"(__float_as_uint(b)));
    return r;
}
__device__ __forceinline__ unsigned long long bcast2(float v) {
    unsigned long long r;
    unsigned u = __float_as_uint(v);
    asm("mov.b64 %0, {%1, %1};" : "=l"(r) : "r"(u));
    return r;
}
__device__ __forceinline__ void fma2(unsigned long long& d, unsigned long long a, unsigned long long b) {
    asm("fma.rn.f32x2 %0, %1, %2, %0;" : "+l"(d) : "l"(a), "l"(b));
}
__device__ __forceinline__ void add2(unsigned long long& d, unsigned long long a) {
    asm("add.rn.f32x2 %0, %0, %1;" : "+l"(d) : "l"(a));
}
__device__ __forceinline__ float2 unpk(unsigned long long v) {
    unsigned lo, hi;
    asm("mov.b64 {%0, %1}, %2;" : "=r"(lo), "=r"(hi) : "l"(v));
    return make_float2(__uint_as_float(lo), __uint_as_float(hi));
}
__device__ __forceinline__ unsigned smem_u32(const void* p) {
    unsigned r;
    asm("{ .reg .u64 t; cvta.to.shared.u64 t, %1; cvt.u32.u64 %0, t; }" : "=r"(r) : "l"(p));
    return r;
}
__device__ __forceinline__ unsigned ctarank() {
    unsigned r;
    asm("mov.u32 %0, %%cluster_ctarank;" : "=r"(r));
    return r;
}
__device__ __forceinline__ void split1(float v, __nv_bfloat16& h, __nv_bfloat16& l) {
    h = __float2bfloat16_rn(v);
    l = __float2bfloat16_rn(v - __bfloat162float(h));
}
__device__ __forceinline__ void ldsm4(unsigned* r, uint32_t addr) {
    asm volatile("ldmatrix.sync.aligned.m8n8.x4.shared.b16 {%0,%1,%2,%3}, [%4];"
                 : "=r"(r[0]), "=r"(r[1]), "=r"(r[2]), "=r"(r[3]) : "r"(addr));
}
__device__ __forceinline__ void mma_bf16(float* d, const unsigned* a, unsigned b0, unsigned b1) {
    asm volatile(
        "mma.sync.aligned.m16n8k16.row.col.f32.bf16.bf16.f32 "
        "{%0,%1,%2,%3}, {%4,%5,%6,%7}, {%8,%9}, {%0,%1,%2,%3};"
        : "+f"(d[0]), "+f"(d[1]), "+f"(d[2]), "+f"(d[3])
        : "r"(a[0]), "r"(a[1]), "r"(a[2]), "r"(a[3]), "r"(b0), "r"(b1));
}
__device__ __forceinline__ void cvt8(const float* f, uint4& hi4, uint4& lo4) {
    unsigned h[4], l[4];
#pragma unroll
    for (int i = 0; i < 4; i++) {
        __nv_bfloat16 h0, l0, h1, l1;
        split1(f[2 * i], h0, l0);
        split1(f[2 * i + 1], h1, l1);
        h[i] = (unsigned)__bfloat16_as_ushort(h0) | ((unsigned)__bfloat16_as_ushort(h1) << 16);
        l[i] = (unsigned)__bfloat16_as_ushort(l0) | ((unsigned)__bfloat16_as_ushort(l1) << 16);
    }
    hi4 = make_uint4(h[0], h[1], h[2], h[3]);
    lo4 = make_uint4(l[0], l[1], l[2], l[3]);
}
__device__ __forceinline__ void load_pair_f32(const float* src, uint4& h4, uint4& l4) {
    float f[8];
    *(float4*)f = *(const float4*)src;
    *(float4*)(f + 4) = *(const float4*)(src + 4);
    cvt8(f, h4, l4);
}
__device__ __forceinline__ unsigned pack_hilo(float a, float b, unsigned& lo_out) {
    __nv_bfloat16 h0, l0, h1, l1;
    split1(a, h0, l0);
    split1(b, h1, l1);
    lo_out = (unsigned)__bfloat16_as_ushort(l0) | ((unsigned)__bfloat16_as_ushort(l1) << 16);
    return (unsigned)__bfloat16_as_ushort(h0) | ((unsigned)__bfloat16_as_ushort(h1) << 16);
}
__device__ __forceinline__ float bf2f(__nv_bfloat16 v) { return __bfloat162float(v); }
__device__ __forceinline__ void cp16(uint32_t dst, const void* src) {
    asm volatile("cp.async.cg.shared.global [%0], [%1], 16;" :: "r"(dst), "l"(src) : "memory");
}

// ---------------- A_eff prep (writes g_P[0]) ----------------
__global__ void build_aeff_kernel(const float* __restrict__ Aw, const float* __restrict__ Asc) {
    int r = blockIdx.x, c = threadIdx.x;
    __shared__ float red[256];
    float w = Aw[r * 256 + c];
    red[c] = w;
    __syncthreads();
#pragma unroll
    for (int s = 128; s > 0; s >>= 1) {
        if (c < s) red[c] = fmaxf(red[c], red[c + s]);
        __syncthreads();
    }
    float mx = red[0];
    __syncthreads();
    float e = expf(w - mx);
    red[c] = e;
    __syncthreads();
#pragma unroll
    for (int s = 128; s > 0; s >>= 1) {
        if (c < s) red[c] += red[c + s];
        __syncthreads();
    }
    float p = e / red[0];
    float sg = 1.f / (1.f + expf(-Asc[r * 256 + c]));
    g_P[c * 256 + r] = (1.f - 0.1f * sg) * p;
}

// ---------------- matrix powers ----------------
__global__ void pow_kernel(int lsrc, int rfirst, int dstfirst) {
    int row = blockIdx.x, i = threadIdx.x, z = blockIdx.z;
    const float* L = g_P + (size_t)lsrc * 65536;
    const float* R = g_P + (size_t)(rfirst + z) * 65536;
    float* Cd = g_P + (size_t)(dstfirst + z) * 65536;
    __shared__ float Lrow[256];
    Lrow[i] = L[row * 256 + i];
    __syncthreads();
    float a0 = 0, a1 = 0, a2 = 0, a3 = 0;
#pragma unroll 8
    for (int m = 0; m < 256; m += 4) {
        a0 = fmaf(Lrow[m + 0], R[(m + 0) * 256 + i], a0);
        a1 = fmaf(Lrow[m + 1], R[(m + 1) * 256 + i], a1);
        a2 = fmaf(Lrow[m + 2], R[(m + 2) * 256 + i], a2);
        a3 = fmaf(Lrow[m + 3], R[(m + 3) * 256 + i], a3);
    }
    Cd[row * 256 + i] = (a0 + a1) + (a2 + a3);
}

// ---------------- transpose+split powers ----------------
__global__ void transp_kernel() {
    int k = blockIdx.x;
    int kt = blockIdx.y * 32;
    int nt = blockIdx.z * 32;
    int tx = threadIdx.x, ty = threadIdx.y;
    __shared__ float tile[32][33];
    const float* P = g_P + (size_t)k * 65536;
#pragma unroll
    for (int r = 0; r < 4; r++) {
        int kk = kt + ty + r * 8;
        tile[ty + r * 8][tx] = P[kk * 256 + nt + tx];
    }
    __syncthreads();
#pragma unroll
    for (int r = 0; r < 4; r++) {
        int n = nt + ty + r * 8;
        float v = tile[tx][ty + r * 8];
        __nv_bfloat16 h, l;
        split1(v, h, l);
        size_t o = (size_t)k * 65536 + (size_t)n * 256 + kt + tx;
        g_PT_hi[o] = h;
        g_PT_lo[o] = l;
    }
}

// ---------------- pre-split converts ----------------
__global__ void convert_mu_kernel(const float* __restrict__ Mf, const float* __restrict__ DT) {
    size_t gid = (size_t)blockIdx.x * 256 + threadIdx.x;  // 131072*32 groups of 8
    size_t m = gid >> 5;
    int c8 = (int)(gid & 31) * 8;
    const float* src = (c8 < 128) ? Mf + m * 128 + c8 : DT + m * 128 + (c8 - 128);
    uint4 h, l;
    load_pair_f32(src, h, l);
    *(uint4*)(g_mu_hi + m * 256 + c8) = h;
    *(uint4*)(g_mu_lo + m * 256 + c8) = l;
}
__global__ void convert_D_kernel(const float* __restrict__ D) {
    size_t gid = (size_t)blockIdx.x * 256 + threadIdx.x;  // 131072*16 groups
    size_t m = gid >> 4;
    int c8 = (int)(gid & 15) * 8;
    uint4 h, l;
    load_pair_f32(D + m * 128 + c8, h, l);
    *(uint4*)(g_D_hi + m * 128 + c8) = h;
    *(uint4*)(g_D_lo + m * 128 + c8) = l;
}
__global__ void convert_w_kernel(const float* __restrict__ hf1, const float* __restrict__ hf2,
                                 const float* __restrict__ BW, const float* __restrict__ EW) {
    int id = blockIdx.x * 256 + threadIdx.x;  // 0..131071
    if (blockIdx.y == 0) {
        __nv_bfloat16 h, l;
        split1(hf1[id], h, l);
        g_w1_hi[id] = h;
        g_w1_lo[id] = l;
    } else if (blockIdx.y == 1) {
        __nv_bfloat16 h, l;
        split1(hf2[id], h, l);
        g_w2_hi[id] = h;
        g_w2_lo[id] = l;
    } else {
        if (id < 256 * 384) {
            int n = id / 384, k = id % 384;
            float v = (k < 256) ? BW[n * 256 + k] : EW[n * 128 + (k - 256)];
            __nv_bfloat16 h, l;
            split1(v, h, l);
            g_be_hi[id] = h;
            g_be_lo[id] = l;
        }
    }
}

// ---------------- unified cp.async-pipelined HMMA GEMM ----------------
// MODE 0: A=g_mu K=256, B=g_w1, N=512 -> g_h hi/lo = relu
// MODE 1: A=g_h K=512, B=g_w2, N=256 -> g_u hi/lo = relu, Su_min/max
// MODE 2: A=g_u|g_D K=384, B=g_be, N=256 -> drive to out X, + fused c0 copy
// MODE 3: csweep: A=g_c[j-1] K=256, B=PT[0] -> c_j = C + drive_t
// MODE 4: recon:  A=g_s K=256, B=PT[j] (j=blockIdx.z) -> X,Sx,Y epilogue
static constexpr int SROW = 80;                    // 32 bf16 + 16B pad
static constexpr uint32_t AHI = 0, ALO = 10240, BHI = 20480, BLO = 30720;
static constexpr uint32_t STG = 40960;
static constexpr int GSMEM = 2 * (int)STG;         // 81920

template <int MODE>
__global__ void __launch_bounds__(256, 2)
gemm_mma_kernel(const float* __restrict__ p4, const float* __restrict__ p5,
                float* __restrict__ out, int jparam) {
    constexpr int K = (MODE == 0) ? 256 : (MODE == 1) ? 512 : (MODE == 2) ? 384 : 256;
    constexpr int NCH = K / 32;

    extern __shared__ char smem[];
    uint32_t sbu = smem_u32(smem);

    int tid = threadIdx.x;
    int lane = tid & 31;
    int wid = tid >> 5;
    int wm = wid & 3;
    int wn = wid >> 2;
    int m0 = blockIdx.y * 128;
    int n0 = blockIdx.x * 128;
    int jv = (MODE == 4) ? (int)blockIdx.z : jparam;

    auto cpTile = [&](int kc) {
        int k0 = kc * 32;
        uint32_t sbase = sbu + (uint32_t)(kc & 1) * STG;
        const __nv_bfloat16 *ah, *al;
        size_t sa;
        int ka;
        if constexpr (MODE == 0) { ah = g_mu_hi; al = g_mu_lo; sa = 256; ka = k0; }
        else if constexpr (MODE == 1) { ah = g_h_hi; al = g_h_lo; sa = 512; ka = k0; }
        else if constexpr (MODE == 2) {
            if (k0 < 256) { ah = g_u_hi; al = g_u_lo; sa = 256; ka = k0; }
            else { ah = g_D_hi; al = g_D_lo; sa = 128; ka = k0 - 256; }
        } else if constexpr (MODE == 3) {
            ah = g_h_hi + (size_t)(jv - 1) * CSTRIDE;
            al = g_h_lo + (size_t)(jv - 1) * CSTRIDE;
            sa = 256; ka = k0;
        } else { ah = g_u_hi; al = g_u_lo; sa = 256; ka = k0; }
        const __nv_bfloat16 *bh, *bl;
        size_t sbn;
        if constexpr (MODE == 0) { bh = g_w1_hi; bl = g_w1_lo; sbn = 256; }
        else if constexpr (MODE == 1) { bh = g_w2_hi; bl = g_w2_lo; sbn = 512; }
        else if constexpr (MODE == 2) { bh = g_be_hi; bl = g_be_lo; sbn = 384; }
        else if constexpr (MODE == 3) { bh = g_PT_hi; bl = g_PT_lo; sbn = 256; }
        else { bh = g_PT_hi + (size_t)jv * 65536; bl = g_PT_lo + (size_t)jv * 65536; sbn = 256; }
#pragma unroll
        for (int it = 0; it < 2; it++) {
            int g = it * 256 + tid;
            int row = g >> 2, cc = g & 3;
            uint32_t so = (uint32_t)(row * SROW + cc * 16);
            cp16(sbase + AHI + so, ah + (size_t)(m0 + row) * sa + ka + cc * 8);
            cp16(sbase + ALO + so, al + (size_t)(m0 + row) * sa + ka + cc * 8);
            cp16(sbase + BHI + so, bh + (size_t)(n0 + row) * sbn + k0 + cc * 8);
            cp16(sbase + BLO + so, bl + (size_t)(n0 + row) * sbn + k0 + cc * 8);
        }
        asm volatile("cp.async.commit_group;" ::: "memory");
    };

    uint32_t a_off = (uint32_t)((lane & 15) * SROW + ((lane >> 4) << 3) * 2);
    uint32_t b_off = (uint32_t)((((lane & 7) | ((lane >> 4) << 3))) * SROW +
                                (((lane >> 3) & 1) << 3) * 2);

    float d[2][8][4];
#pragma unroll
    for (int i = 0; i < 2; i++)
#pragma unroll
        for (int jq = 0; jq < 8; jq++)
#pragma unroll
            for (int kq = 0; kq < 4; kq++) d[i][jq][kq] = 0.f;

    auto mmaChunk = [&](int stg) {
        uint32_t bs = sbu + (uint32_t)stg * STG;
#pragma unroll
        for (int ks = 0; ks < 2; ks++) {
            unsigned ah[2][4], al[2][4];
#pragma unroll
            for (int mt = 0; mt < 2; mt++) {
                uint32_t base = bs + (uint32_t)((wm * 32 + mt * 16) * SROW + ks * 32) + a_off;
                ldsm4(ah[mt], base + AHI);
                ldsm4(al[mt], base + ALO);
            }
#pragma unroll
            for (int nt = 0; nt < 4; nt++) {
                unsigned bh[4], bl[4];
                uint32_t base = bs + (uint32_t)((wn * 64 + nt * 16) * SROW + ks * 32) + b_off;
                ldsm4(bh, base + BHI);
                ldsm4(bl, base + BLO);
#pragma unroll
                for (int mt = 0; mt < 2; mt++) {
#pragma unroll
                    for (int nn = 0; nn < 2; nn++) {
                        float* dd = d[mt][nt * 2 + nn];
                        mma_bf16(dd, ah[mt], bh[2 * nn], bh[2 * nn + 1]);
                        mma_bf16(dd, ah[mt], bl[2 * nn], bl[2 * nn + 1]);
                        mma_bf16(dd, al[mt], bh[2 * nn], bh[2 * nn + 1]);
                    }
                }
            }
        }
    };

    // cp.async 2-stage mainloop
    cpTile(0);
    for (int kc = 0; kc < NCH; kc++) {
        if (kc + 1 < NCH) {
            cpTile(kc + 1);
            asm volatile("cp.async.wait_group 1;" ::: "memory");
        } else {
            asm volatile("cp.async.wait_group 0;" ::: "memory");
        }
        __syncthreads();
        mmaChunk(kc & 1);
        __syncthreads();
    }

    // ---- epilogue ----
    int g = lane >> 2, q = lane & 3;
#pragma unroll
    for (int mt = 0; mt < 2; mt++) {
        int r0 = m0 + wm * 32 + mt * 16 + g;
#pragma unroll
        for (int jq = 0; jq < 8; jq++) {
            int c = n0 + wn * 64 + jq * 8 + 2 * q;
            float* dd = d[mt][jq];
#pragma unroll
            for (int h = 0; h < 2; h++) {
                int m = r0 + h * 8;
                float v0 = dd[2 * h], v1 = dd[2 * h + 1];
                if constexpr (MODE == 0) {
                    float u0 = fmaxf(v0, 0.f), u1 = fmaxf(v1, 0.f);
                    size_t idx = (size_t)m * 512 + c;
                    unsigned lp, hp = pack_hilo(u0, u1, lp);
                    *(unsigned*)(g_h_hi + idx) = hp;
                    *(unsigned*)(g_h_lo + idx) = lp;
                } else if constexpr (MODE == 1) {
                    float u0 = fmaxf(v0, 0.f), u1 = fmaxf(v1, 0.f);
                    size_t idx = (size_t)m * 256 + c;
                    unsigned lp, hp = pack_hilo(u0, u1, lp);
                    *(unsigned*)(g_u_hi + idx) = hp;
                    *(unsigned*)(g_u_lo + idx) = lp;
                    float2 mn = *(const float2*)(p4 + idx);
                    float2 mx = *(const float2*)(p5 + idx);
                    *(float2*)(out + SUMIN_OFF + idx) =
                        make_float2(fmaxf(mn.x - u0, 0.f), fmaxf(mn.y - u1, 0.f));
                    *(float2*)(out + SUMAX_OFF + idx) =
                        make_float2(fmaxf(u0 - mx.x, 0.f), fmaxf(u1 - mx.y, 0.f));
                } else if constexpr (MODE == 2) {
                    size_t idx = (size_t)m * 256 + c;
                    *(float2*)(out + X_OFF + idx) = make_float2(v0, v1);
                    int trow = m >> 8;
                    if ((trow & 7) == 0) {  // fused c0 init: drive at t=8b
                        int b = trow >> 3, batch = m & 255;
                        size_t ci = ((size_t)b * 256 + batch) * 256 + c;
                        unsigned lp, hp = pack_hilo(v0, v1, lp);
                        *(unsigned*)(g_h_hi + ci) = hp;
                        *(unsigned*)(g_h_lo + ci) = lp;
                    }
                } else if constexpr (MODE == 3) {
                    int b = m >> 8, batch = m & 255;
                    int t = 8 * b + jv;
                    size_t xidx = (((size_t)t * 256) + batch) * 256 + c;
                    size_t ci = (size_t)jv * CSTRIDE + (size_t)m * 256 + c;
                    float2 dr = *(const float2*)(out + X_OFF + xidx);
                    float s0 = v0 + dr.x, s1 = v1 + dr.y;
                    unsigned lp, hp = pack_hilo(s0, s1, lp);
                    *(unsigned*)(g_h_hi + ci) = hp;
                    *(unsigned*)(g_h_lo + ci) = lp;
                } else {
                    int b = m >> 8, batch = m & 255;
                    int t = 8 * b + jv;
                    size_t xidx = (((size_t)t * 256) + batch) * 256 + c;
                    size_t ci = (size_t)jv * CSTRIDE + (size_t)m * 256 + c;
                    unsigned chp = *(const unsigned*)(g_h_hi + ci);
                    unsigned clp = *(const unsigned*)(g_h_lo + ci);
                    __nv_bfloat162 ch = *(__nv_bfloat162*)&chp;
                    __nv_bfloat162 cl = *(__nv_bfloat162*)&clp;
                    float xv0 = v0 + bf2f(__low2bfloat16(ch)) + bf2f(__low2bfloat16(cl));
                    float xv1 = v1 + bf2f(__high2bfloat16(ch)) + bf2f(__high2bfloat16(cl));
                    *(float2*)(out + X_OFF + xidx) = make_float2(xv0, xv1);
                    float2 mn = *(const float2*)(p4 + xidx);
                    float2 mx = *(const float2*)(p5 + xidx);
                    *(float2*)(out + SXMIN_OFF + xidx) =
                        make_float2(fmaxf(mn.x - xv0, 0.f), fmaxf(mn.y - xv1, 0.f));
                    *(float2*)(out + SXMAX_OFF + xidx) =
                        make_float2(fmaxf(xv0 - mx.x, 0.f), fmaxf(xv1 - mx.y, 0.f));
                    if (c == 254) out[Y_OFF + (size_t)t * 256 + batch] = xv1;
                }
            }
        }
    }
}

// ---------------- carry scan: s_{b+1} = s_b @ A^8 + c_{b,7}, 63 steps ----------------
struct ScanSmem {
    float A[256][128];
    ulonglong2 xs2[2][256];
    unsigned long long part[4][64][2][2];
};

__global__ void __launch_bounds__(256, 1) __cluster_dims__(2, 1, 1)
carry_scan_kernel(const float* __restrict__ x0) {
    extern __shared__ char smem_raw[];
    ScanSmem* S = reinterpret_cast<ScanSmem*>(smem_raw);
    int tid = threadIdx.x;
    unsigned rank = ctarank();
    int b0 = (int)(blockIdx.x >> 1) * 4;

    const float* A8 = g_P + 7 * 65536;
#pragma unroll
    for (int it = 0; it < 32; it++) {
        int idx4 = tid + it * 256;
        int jq = idx4 >> 5;
        int c4 = idx4 & 31;
        float4 v = *(const float4*)(A8 + (size_t)jq * 256 + rank * 128 + c4 * 4);
        *(float4*)(&S->A[jq][c4 * 4]) = v;
    }
    {
        int jq = tid;
        float a[4];
#pragma unroll
        for (int r = 0; r < 4; r++) {
            a[r] = x0[(b0 + r) * 256 + jq];
            __nv_bfloat16 h, l;
            split1(a[r], h, l);
            size_t si = (size_t)(b0 + r) * 256 + jq;
            g_u_hi[si] = h;
            g_u_lo[si] = l;
        }
        S->xs2[0][jq] = make_ulonglong2(pk2(a[0], a[1]), pk2(a[2], a[3]));
    }
    __syncthreads();

    const int jj = tid >> 6;
    const int cp = tid & 63;
    const int il = tid & 127;
    const int h  = tid >> 7;
    const int gcol = (int)rank * 128 + il;

    const __nv_bfloat16* c7h = g_h_hi + (size_t)7 * CSTRIDE;
    const __nv_bfloat16* c7l = g_h_lo + (size_t)7 * CSTRIDE;

    float pf_d0, pf_d1;
    {
        size_t ci = ((size_t)(b0 + 2 * h)) * 256 + gcol;
        pf_d0 = bf2f(c7h[ci]) + bf2f(c7l[ci]);
        pf_d1 = bf2f(c7h[ci + 256]) + bf2f(c7l[ci + 256]);
    }

    for (int b = 0; b < 63; b++) {
        int p = b & 1;
        unsigned long long a00 = 0, a01 = 0, a10 = 0, a11 = 0;
        const ulonglong2* xb = S->xs2[p];
        const float2* Arow = (const float2*)&S->A[jj * 64][0] + cp;
#pragma unroll 8
        for (int it = 0; it < 64; it++) {
            int jq = jj * 64 + it;
            float2 a = Arow[(size_t)it * 64];
            ulonglong2 xv = xb[jq];
            unsigned long long b0p = bcast2(a.x), b1p = bcast2(a.y);
            fma2(a00, b0p, xv.x);
            fma2(a01, b0p, xv.y);
            fma2(a10, b1p, xv.x);
            fma2(a11, b1p, xv.y);
        }
        S->part[jj][cp][0][0] = a00;
        S->part[jj][cp][0][1] = a01;
        S->part[jj][cp][1][0] = a10;
        S->part[jj][cp][1][1] = a11;
        __syncthreads();

        int cp2 = il >> 1, cip = il & 1;
        unsigned long long s = S->part[0][cp2][cip][h];
        add2(s, S->part[1][cp2][cip][h]);
        add2(s, S->part[2][cp2][cip][h]);
        add2(s, S->part[3][cp2][cip][h]);
        float2 sv = unpk(s);
        float v0 = sv.x + pf_d0;
        float v1 = sv.y + pf_d1;

        {
            size_t row0 = (size_t)(b + 1) * 256 + b0 + 2 * h;
            __nv_bfloat16 hh, ll;
            split1(v0, hh, ll);
            g_u_hi[row0 * 256 + gcol] = hh;
            g_u_lo[row0 * 256 + gcol] = ll;
            split1(v1, hh, ll);
            g_u_hi[(row0 + 1) * 256 + gcol] = hh;
            g_u_lo[(row0 + 1) * 256 + gcol] = ll;
        }

        unsigned long long xn = pk2(v0, v1);
        unsigned long long* dst =
            (h == 0) ? &S->xs2[p ^ 1][gcol].x : &S->xs2[p ^ 1][gcol].y;
        *dst = xn;
        unsigned laddr = smem_u32(dst);
        unsigned raddr;
        asm("mapa.shared::cluster.u32 %0, %1, %2;" : "=r"(raddr) : "r"(laddr), "r"(rank ^ 1u));
        asm volatile("st.shared::cluster.u64 [%0], %1;" :: "r"(raddr), "l"(xn) : "memory");

        int bn = (b < 62) ? b + 1 : 62;
        size_t cin = ((size_t)bn * 256 + b0 + 2 * h) * 256 + gcol;
        pf_d0 = bf2f(c7h[cin]) + bf2f(c7l[cin]);
        pf_d1 = bf2f(c7h[cin + 256]) + bf2f(c7l[cin + 256]);

        asm volatile("barrier.cluster.arrive.aligned;" ::: "memory");
        asm volatile("barrier.cluster.wait.aligned;" ::: "memory");
    }
}

// ---------------- launch ----------------
extern "C" void kernel_launch(void* const* d_in, const int* in_sizes, int n_in,
                              void* d_out, int out_size) {
    const float* x      = (const float*)d_in[0];
    const float* M_flow = (const float*)d_in[1];
    const float* DT     = (const float*)d_in[2];
    const float* D      = (const float*)d_in[3];
    const float* XMIN   = (const float*)d_in[4];
    const float* XMAX   = (const float*)d_in[5];
    const float* UMIN   = (const float*)d_in[6];
    const float* UMAX   = (const float*)d_in[7];
    const float* A_w    = (const float*)d_in[8];
    const float* A_sc   = (const float*)d_in[9];
    const float* B_W    = (const float*)d_in[10];
    const float* E_W    = (const float*)d_in[11];
    const float* hf1_W  = (const float*)d_in[12];
    const float* hf2_W  = (const float*)d_in[13];
    float* out = (float*)d_out;

    build_aeff_kernel<<<256, 256>>>(A_w, A_sc);
    pow_kernel<<<dim3(256, 1, 1), 256>>>(0, 0, 1);
    pow_kernel<<<dim3(256, 1, 2), 256>>>(1, 0, 2);
    pow_kernel<<<dim3(256, 1, 4), 256>>>(3, 0, 4);
    transp_kernel<<<dim3(8, 8, 8), dim3(32, 8)>>>();

    convert_mu_kernel<<<16384, 256>>>(M_flow, DT);
    convert_D_kernel<<<8192, 256>>>(D);
    convert_w_kernel<<<dim3(512, 3), 256>>>(hf1_W, hf2_W, B_W, E_W);

    cudaFuncSetAttribute(gemm_mma_kernel<0>, cudaFuncAttributeMaxDynamicSharedMemorySize, GSMEM);
    cudaFuncSetAttribute(gemm_mma_kernel<1>, cudaFuncAttributeMaxDynamicSharedMemorySize, GSMEM);
    cudaFuncSetAttribute(gemm_mma_kernel<2>, cudaFuncAttributeMaxDynamicSharedMemorySize, GSMEM);
    cudaFuncSetAttribute(gemm_mma_kernel<3>, cudaFuncAttributeMaxDynamicSharedMemorySize, GSMEM);
    cudaFuncSetAttribute(gemm_mma_kernel<4>, cudaFuncAttributeMaxDynamicSharedMemorySize, GSMEM);

    gemm_mma_kernel<0><<<dim3(4, 1024), 256, GSMEM>>>(nullptr, nullptr, out, 0);
    gemm_mma_kernel<1><<<dim3(2, 1024), 256, GSMEM>>>(UMIN, UMAX, out, 0);
    gemm_mma_kernel<2><<<dim3(2, 1024), 256, GSMEM>>>(nullptr, nullptr, out, 0);

    for (int j = 1; j <= 7; j++)
        gemm_mma_kernel<3><<<dim3(2, 128), 256, GSMEM>>>(nullptr, nullptr, out, j);

    cudaFuncSetAttribute(carry_scan_kernel, cudaFuncAttributeMaxDynamicSharedMemorySize,
                         (int)sizeof(ScanSmem));
    carry_scan_kernel<<<128, 256, sizeof(ScanSmem)>>>(x);

    gemm_mma_kernel<4><<<dim3(2, 128, 8), 256, GSMEM>>>(XMIN, XMAX, out, 0);
}

// round 10
// speedup vs baseline: 1.2163x; 1.1121x over previous
#include <cuda_runtime.h>
#include <cuda_bf16.h>
#include <cuda_fp16.h>
#include <cstdint>
#include <cstddef>

// T=512, B=256, NX=256, NU=256, ND=128, NM=128, NDT=128, NH=512, M=T*B=131072
static constexpr size_t X_OFF     = 0;
static constexpr size_t Y_OFF     = 33554432;
static constexpr size_t SXMIN_OFF = 33685504;
static constexpr size_t SXMAX_OFF = 67239936;
static constexpr size_t SUMIN_OFF = 100794368;
static constexpr size_t SUMAX_OFF = 134348800;

// Powers: g_P[k][j*256+i] = (A_eff)^(k+1)[j][i]
__device__ float g_P[8 * 65536];
__device__ __nv_bfloat16 g_PT_hi[8 * 65536];  // g_PT[k][n*256+kk] = P_k[kk][n]
__device__ __nv_bfloat16 g_PT_lo[8 * 65536];

// h: fp16 single-precision-split hi only (mode0 out, mode1 in). Reused later as
// c-scratch (bf16 pairs) once mode1 has consumed it.
__device__ __half g_h[(size_t)131072 * 512];
__device__ __nv_bfloat16 g_u_hi[(size_t)131072 * 256];
__device__ __nv_bfloat16 g_u_lo[(size_t)131072 * 256];

static constexpr size_t CSTRIDE = (size_t)16384 * 256;
__device__ __forceinline__ __nv_bfloat16* c_hi(int j) {
    return ((__nv_bfloat16*)g_h) + (size_t)j * 2 * CSTRIDE;
}
__device__ __forceinline__ __nv_bfloat16* c_lo(int j) {
    return ((__nv_bfloat16*)g_h) + (size_t)j * 2 * CSTRIDE + CSTRIDE;
}

// ---------------- scalar helpers ----------------
__device__ __forceinline__ unsigned long long pk2(float a, float b) {
    unsigned long long r;
    asm("mov.b64 %0, {%1, %2};" : "=l"(r) : "r"(__float_as_uint(a)), "r"(__float_as_uint(b)));
    return r;
}
__device__ __forceinline__ unsigned long long bcast2(float v) {
    unsigned long long r;
    unsigned u = __float_as_uint(v);
    asm("mov.b64 %0, {%1, %1};" : "=l"(r) : "r"(u));
    return r;
}
__device__ __forceinline__ void fma2(unsigned long long& d, unsigned long long a, unsigned long long b) {
    asm("fma.rn.f32x2 %0, %1, %2, %0;" : "+l"(d) : "l"(a), "l"(b));
}
__device__ __forceinline__ void add2(unsigned long long& d, unsigned long long a) {
    asm("add.rn.f32x2 %0, %0, %1;" : "+l"(d) : "l"(a));
}
__device__ __forceinline__ float2 unpk(unsigned long long v) {
    unsigned lo, hi;
    asm("mov.b64 {%0, %1}, %2;" : "=r"(lo), "=r"(hi) : "l"(v));
    return make_float2(__uint_as_float(lo), __uint_as_float(hi));
}
__device__ __forceinline__ unsigned smem_u32(const void* p) {
    unsigned r;
    asm("{ .reg .u64 t; cvta.to.shared.u64 t, %1; cvt.u32.u64 %0, t; }" : "=r"(r) : "l"(p));
    return r;
}
__device__ __forceinline__ unsigned ctarank() {
    unsigned r;
    asm("mov.u32 %0, %%cluster_ctarank;" : "=r"(r));
    return r;
}
__device__ __forceinline__ void split1(float v, __nv_bfloat16& h, __nv_bfloat16& l) {
    h = __float2bfloat16_rn(v);
    l = __float2bfloat16_rn(v - __bfloat162float(h));
}
__device__ __forceinline__ void ldsm4(unsigned* r, uint32_t addr) {
    asm volatile("ldmatrix.sync.aligned.m8n8.x4.shared.b16 {%0,%1,%2,%3}, [%4];"
                 : "=r"(r[0]), "=r"(r[1]), "=r"(r[2]), "=r"(r[3]) : "r"(addr));
}
__device__ __forceinline__ void mma_bf16(float* d, const unsigned* a, unsigned b0, unsigned b1) {
    asm volatile(
        "mma.sync.aligned.m16n8k16.row.col.f32.bf16.bf16.f32 "
        "{%0,%1,%2,%3}, {%4,%5,%6,%7}, {%8,%9}, {%0,%1,%2,%3};"
        : "+f"(d[0]), "+f"(d[1]), "+f"(d[2]), "+f"(d[3])
        : "r"(a[0]), "r"(a[1]), "r"(a[2]), "r"(a[3]), "r"(b0), "r"(b1));
}
__device__ __forceinline__ void mma_f16(float* d, const unsigned* a, unsigned b0, unsigned b1) {
    asm volatile(
        "mma.sync.aligned.m16n8k16.row.col.f32.f16.f16.f32 "
        "{%0,%1,%2,%3}, {%4,%5,%6,%7}, {%8,%9}, {%0,%1,%2,%3};"
        : "+f"(d[0]), "+f"(d[1]), "+f"(d[2]), "+f"(d[3])
        : "r"(a[0]), "r"(a[1]), "r"(a[2]), "r"(a[3]), "r"(b0), "r"(b1));
}
// 8 f32 -> bf16 hi/lo pair (uint4 each)
__device__ __forceinline__ void cvt8(const float* f, uint4& hi4, uint4& lo4) {
    unsigned h[4], l[4];
#pragma unroll
    for (int i = 0; i < 4; i++) {
        __nv_bfloat16 h0, l0, h1, l1;
        split1(f[2 * i], h0, l0);
        split1(f[2 * i + 1], h1, l1);
        h[i] = (unsigned)__bfloat16_as_ushort(h0) | ((unsigned)__bfloat16_as_ushort(h1) << 16);
        l[i] = (unsigned)__bfloat16_as_ushort(l0) | ((unsigned)__bfloat16_as_ushort(l1) << 16);
    }
    hi4 = make_uint4(h[0], h[1], h[2], h[3]);
    lo4 = make_uint4(l[0], l[1], l[2], l[3]);
}
// 8 f32 -> fp16 hi/lo pair
__device__ __forceinline__ void cvt8h(const float* f, uint4& hi4, uint4& lo4) {
    unsigned h[4], l[4];
#pragma unroll
    for (int i = 0; i < 4; i++) {
        __half h0 = __float2half_rn(f[2 * i]);
        __half h1 = __float2half_rn(f[2 * i + 1]);
        __half l0 = __float2half_rn(f[2 * i] - __half2float(h0));
        __half l1 = __float2half_rn(f[2 * i + 1] - __half2float(h1));
        h[i] = (unsigned)__half_as_ushort(h0) | ((unsigned)__half_as_ushort(h1) << 16);
        l[i] = (unsigned)__half_as_ushort(l0) | ((unsigned)__half_as_ushort(l1) << 16);
    }
    hi4 = make_uint4(h[0], h[1], h[2], h[3]);
    lo4 = make_uint4(l[0], l[1], l[2], l[3]);
}
// 8 f32 -> fp16 hi only
__device__ __forceinline__ uint4 cvt8h_hi(const float* f) {
    unsigned h[4];
#pragma unroll
    for (int i = 0; i < 4; i++) {
        __half h0 = __float2half_rn(f[2 * i]);
        __half h1 = __float2half_rn(f[2 * i + 1]);
        h[i] = (unsigned)__half_as_ushort(h0) | ((unsigned)__half_as_ushort(h1) << 16);
    }
    return make_uint4(h[0], h[1], h[2], h[3]);
}
__device__ __forceinline__ void load8f(const float* src, float* f) {
    *(float4*)f = *(const float4*)src;
    *(float4*)(f + 4) = *(const float4*)(src + 4);
}
__device__ __forceinline__ unsigned pack_hilo(float a, float b, unsigned& lo_out) {
    __nv_bfloat16 h0, l0, h1, l1;
    split1(a, h0, l0);
    split1(b, h1, l1);
    lo_out = (unsigned)__bfloat16_as_ushort(l0) | ((unsigned)__bfloat16_as_ushort(l1) << 16);
    return (unsigned)__bfloat16_as_ushort(h0) | ((unsigned)__bfloat16_as_ushort(h1) << 16);
}
__device__ __forceinline__ float bf2f(__nv_bfloat16 v) { return __bfloat162float(v); }

// ---------------- A_eff prep (writes g_P[0]) ----------------
__global__ void build_aeff_kernel(const float* __restrict__ Aw, const float* __restrict__ Asc) {
    int r = blockIdx.x, c = threadIdx.x;
    __shared__ float red[256];
    float w = Aw[r * 256 + c];
    red[c] = w;
    __syncthreads();
#pragma unroll
    for (int s = 128; s > 0; s >>= 1) {
        if (c < s) red[c] = fmaxf(red[c], red[c + s]);
        __syncthreads();
    }
    float mx = red[0];
    __syncthreads();
    float e = expf(w - mx);
    red[c] = e;
    __syncthreads();
#pragma unroll
    for (int s = 128; s > 0; s >>= 1) {
        if (c < s) red[c] += red[c + s];
        __syncthreads();
    }
    float p = e / red[0];
    float sg = 1.f / (1.f + expf(-Asc[r * 256 + c]));
    g_P[c * 256 + r] = (1.f - 0.1f * sg) * p;
}

// ---------------- matrix powers ----------------
__global__ void pow_kernel(int lsrc, int rfirst, int dstfirst) {
    int row = blockIdx.x, i = threadIdx.x, z = blockIdx.z;
    const float* L = g_P + (size_t)lsrc * 65536;
    const float* R = g_P + (size_t)(rfirst + z) * 65536;
    float* Cd = g_P + (size_t)(dstfirst + z) * 65536;
    __shared__ float Lrow[256];
    Lrow[i] = L[row * 256 + i];
    __syncthreads();
    float a0 = 0, a1 = 0, a2 = 0, a3 = 0;
#pragma unroll 8
    for (int m = 0; m < 256; m += 4) {
        a0 = fmaf(Lrow[m + 0], R[(m + 0) * 256 + i], a0);
        a1 = fmaf(Lrow[m + 1], R[(m + 1) * 256 + i], a1);
        a2 = fmaf(Lrow[m + 2], R[(m + 2) * 256 + i], a2);
        a3 = fmaf(Lrow[m + 3], R[(m + 3) * 256 + i], a3);
    }
    Cd[row * 256 + i] = (a0 + a1) + (a2 + a3);
}

// ---------------- transpose+split powers ----------------
__global__ void transp_kernel() {
    int k = blockIdx.x;
    int kt = blockIdx.y * 32;
    int nt = blockIdx.z * 32;
    int tx = threadIdx.x, ty = threadIdx.y;
    __shared__ float tile[32][33];
    const float* P = g_P + (size_t)k * 65536;
#pragma unroll
    for (int r = 0; r < 4; r++) {
        int kk = kt + ty + r * 8;
        tile[ty + r * 8][tx] = P[kk * 256 + nt + tx];
    }
    __syncthreads();
#pragma unroll
    for (int r = 0; r < 4; r++) {
        int n = nt + ty + r * 8;
        float v = tile[tx][ty + r * 8];
        __nv_bfloat16 h, l;
        split1(v, h, l);
        size_t o = (size_t)k * 65536 + (size_t)n * 256 + kt + tx;
        g_PT_hi[o] = h;
        g_PT_lo[o] = l;
    }
}

static constexpr int SROW = 144;  // 64 elems * 2B + 16B pad

// ---------------- fp16 2-term GEMM (modes 0,1: the MLP) ----------------
// MODE 0: A=concat(M_flow,DT) K=256, B=hf1, N=512 -> g_h (fp16) = relu
// MODE 1: A=g_h (fp16) K=512, B=hf2, N=256 -> g_u bf16 pair = relu, Su_min/max
template <int MODE>
__global__ void __launch_bounds__(256, 2)
gemm01_kernel(const float* __restrict__ pA0, const float* __restrict__ pA1,
              const float* __restrict__ pB0,
              const float* __restrict__ pUmin, const float* __restrict__ pUmax,
              float* __restrict__ out) {
    constexpr int K = (MODE == 0) ? 256 : 512;
    constexpr int NCH = K / 64;
    constexpr uint32_t AHI = 0, BHI = 18432, BLO = 36864;

    extern __shared__ char smem[];
    uint32_t sb = smem_u32(smem);

    int tid = threadIdx.x;
    int lane = tid & 31;
    int wid = tid >> 5;
    int wm = wid & 3;
    int wn = wid >> 2;
    int m0 = blockIdx.y * 128;
    int n0 = blockIdx.x * 128;

    uint32_t a_off = (uint32_t)((lane & 15) * SROW + ((lane >> 4) << 3) * 2);
    uint32_t b_off = (uint32_t)((((lane & 7) | ((lane >> 4) << 3))) * SROW +
                                (((lane >> 3) & 1) << 3) * 2);

    float d[2][8][4];
#pragma unroll
    for (int i = 0; i < 2; i++)
#pragma unroll
        for (int jq = 0; jq < 8; jq++)
#pragma unroll
            for (int kq = 0; kq < 4; kq++) d[i][jq][kq] = 0.f;

    for (int kc = 0; kc < NCH; kc++) {
        int k0 = kc * 64;
        __syncthreads();
        // stage A (hi only)
#pragma unroll
        for (int it = 0; it < 4; it++) {
            int g = it * 256 + tid;
            int row = g >> 3, c8 = g & 7;
            int k = k0 + c8 * 8;
            size_t m = (size_t)(m0 + row);
            uint32_t off = (uint32_t)(row * SROW + c8 * 16);
            if constexpr (MODE == 0) {
                const float* src = (k < 128) ? pA0 + m * 128 + k : pA1 + m * 128 + (k - 128);
                float f[8];
                load8f(src, f);
                *(uint4*)(smem + AHI + off) = cvt8h_hi(f);
            } else {
                *(uint4*)(smem + AHI + off) = *(const uint4*)(g_h + m * 512 + k);
            }
        }
        // stage B (pair)
#pragma unroll
        for (int it = 0; it < 4; it++) {
            int g = it * 256 + tid;
            int row = g >> 3, c8 = g & 7;
            int k = k0 + c8 * 8;
            size_t n = (size_t)(n0 + row);
            const float* src = (MODE == 0) ? pB0 + n * 256 + k : pB0 + n * 512 + k;
            float f[8];
            load8f(src, f);
            uint4 hv, lv;
            cvt8h(f, hv, lv);
            uint32_t off = (uint32_t)(row * SROW + c8 * 16);
            *(uint4*)(smem + BHI + off) = hv;
            *(uint4*)(smem + BLO + off) = lv;
        }
        __syncthreads();

#pragma unroll
        for (int ks = 0; ks < 4; ks++) {
            unsigned ah[2][4];
#pragma unroll
            for (int mt = 0; mt < 2; mt++) {
                uint32_t base = sb + (uint32_t)((wm * 32 + mt * 16) * SROW + ks * 32) + a_off;
                ldsm4(ah[mt], base + AHI);
            }
#pragma unroll
            for (int nt = 0; nt < 4; nt++) {
                unsigned bh[4], bl[4];
                uint32_t base = sb + (uint32_t)((wn * 64 + nt * 16) * SROW + ks * 32) + b_off;
                ldsm4(bh, base + BHI);
                ldsm4(bl, base + BLO);
#pragma unroll
                for (int mt = 0; mt < 2; mt++) {
#pragma unroll
                    for (int nn = 0; nn < 2; nn++) {
                        float* dd = d[mt][nt * 2 + nn];
                        mma_f16(dd, ah[mt], bh[2 * nn], bh[2 * nn + 1]);
                        mma_f16(dd, ah[mt], bl[2 * nn], bl[2 * nn + 1]);
                    }
                }
            }
        }
    }

    int g = lane >> 2, q = lane & 3;
#pragma unroll
    for (int mt = 0; mt < 2; mt++) {
        int r0 = m0 + wm * 32 + mt * 16 + g;
#pragma unroll
        for (int jq = 0; jq < 8; jq++) {
            int c = n0 + wn * 64 + jq * 8 + 2 * q;
            float* dd = d[mt][jq];
#pragma unroll
            for (int h = 0; h < 2; h++) {
                size_t m = (size_t)(r0 + h * 8);
                float u0 = fmaxf(dd[2 * h], 0.f), u1 = fmaxf(dd[2 * h + 1], 0.f);
                if constexpr (MODE == 0) {
                    size_t idx = m * 512 + c;
                    unsigned hp = (unsigned)__half_as_ushort(__float2half_rn(u0)) |
                                  ((unsigned)__half_as_ushort(__float2half_rn(u1)) << 16);
                    *(unsigned*)(g_h + idx) = hp;
                } else {
                    size_t idx = m * 256 + c;
                    unsigned lp, hp = pack_hilo(u0, u1, lp);
                    *(unsigned*)(g_u_hi + idx) = hp;
                    *(unsigned*)(g_u_lo + idx) = lp;
                    float2 mn = *(const float2*)(pUmin + idx);
                    float2 mx = *(const float2*)(pUmax + idx);
                    *(float2*)(out + SUMIN_OFF + idx) =
                        make_float2(fmaxf(mn.x - u0, 0.f), fmaxf(mn.y - u1, 0.f));
                    *(float2*)(out + SUMAX_OFF + idx) =
                        make_float2(fmaxf(u0 - mx.x, 0.f), fmaxf(u1 - mx.y, 0.f));
                }
            }
        }
    }
}

// ---------------- bf16 3-term GEMM (modes 2,3,4: drive + block scan) ----------------
// MODE 2: A=concat(g_u,D) K=384, B=concat(B_W,E_W), N=256 -> drive to out X + fused c0
// MODE 3: csweep: A=c(j-1) K=256, B=PT[0] -> c(j) = C + drive_t
// MODE 4: recon:  A=s (g_u) K=256, B=PT[j], j=blockIdx.z -> X,Sx,Y epilogue
template <int MODE>
__global__ void __launch_bounds__(256, 2)
gemm_bf_kernel(const float* __restrict__ pA1, const float* __restrict__ pB0,
               const float* __restrict__ pB1,
               const float* __restrict__ p4, const float* __restrict__ p5,
               float* __restrict__ out, int jparam) {
    constexpr int K = (MODE == 2) ? 384 : 256;
    constexpr int NCH = K / 64;
    constexpr uint32_t AHI = 0, ALO = 18432, BHI = 36864, BLO = 55296;

    extern __shared__ char smem[];
    uint32_t sb = smem_u32(smem);

    int tid = threadIdx.x;
    int lane = tid & 31;
    int wid = tid >> 5;
    int wm = wid & 3;
    int wn = wid >> 2;
    int m0 = blockIdx.y * 128;
    int n0 = blockIdx.x * 128;
    int jv = (MODE == 4) ? (int)blockIdx.z : jparam;

    const __nv_bfloat16* Ahi = nullptr;
    const __nv_bfloat16* Alo = nullptr;
    const __nv_bfloat16* Bhi = nullptr;
    const __nv_bfloat16* Blo = nullptr;
    if constexpr (MODE == 3) {
        Ahi = c_hi(jv - 1);
        Alo = c_lo(jv - 1);
        Bhi = g_PT_hi;
        Blo = g_PT_lo;
    } else if constexpr (MODE == 4) {
        Ahi = g_u_hi;
        Alo = g_u_lo;
        Bhi = g_PT_hi + (size_t)jv * 65536;
        Blo = g_PT_lo + (size_t)jv * 65536;
    }

    uint32_t a_off = (uint32_t)((lane & 15) * SROW + ((lane >> 4) << 3) * 2);
    uint32_t b_off = (uint32_t)((((lane & 7) | ((lane >> 4) << 3))) * SROW +
                                (((lane >> 3) & 1) << 3) * 2);

    float d[2][8][4];
#pragma unroll
    for (int i = 0; i < 2; i++)
#pragma unroll
        for (int jq = 0; jq < 8; jq++)
#pragma unroll
            for (int kq = 0; kq < 4; kq++) d[i][jq][kq] = 0.f;

    for (int kc = 0; kc < NCH; kc++) {
        int k0 = kc * 64;
        __syncthreads();
        // stage A
#pragma unroll
        for (int it = 0; it < 4; it++) {
            int g = it * 256 + tid;
            int row = g >> 3, c8 = g & 7;
            int k = k0 + c8 * 8;
            size_t m = (size_t)(m0 + row);
            uint32_t off = (uint32_t)(row * SROW + c8 * 16);
            if constexpr (MODE == 2) {
                if (k < 256) {
                    size_t gi = m * 256 + k;
                    *(uint4*)(smem + AHI + off) = *(const uint4*)(g_u_hi + gi);
                    *(uint4*)(smem + ALO + off) = *(const uint4*)(g_u_lo + gi);
                } else {
                    float f[8];
                    load8f(pA1 + m * 128 + (k - 256), f);
                    uint4 hv, lv;
                    cvt8(f, hv, lv);
                    *(uint4*)(smem + AHI + off) = hv;
                    *(uint4*)(smem + ALO + off) = lv;
                }
            } else {
                size_t gi = m * 256 + k;
                *(uint4*)(smem + AHI + off) = *(const uint4*)(Ahi + gi);
                *(uint4*)(smem + ALO + off) = *(const uint4*)(Alo + gi);
            }
        }
        // stage B
#pragma unroll
        for (int it = 0; it < 4; it++) {
            int g = it * 256 + tid;
            int row = g >> 3, c8 = g & 7;
            int k = k0 + c8 * 8;
            size_t n = (size_t)(n0 + row);
            uint32_t off = (uint32_t)(row * SROW + c8 * 16);
            if constexpr (MODE == 2) {
                const float* src = (k < 256) ? pB0 + n * 256 + k : pB1 + n * 128 + (k - 256);
                float f[8];
                load8f(src, f);
                uint4 hv, lv;
                cvt8(f, hv, lv);
                *(uint4*)(smem + BHI + off) = hv;
                *(uint4*)(smem + BLO + off) = lv;
            } else {
                size_t bi = n * 256 + k;
                *(uint4*)(smem + BHI + off) = *(const uint4*)(Bhi + bi);
                *(uint4*)(smem + BLO + off) = *(const uint4*)(Blo + bi);
            }
        }
        __syncthreads();

#pragma unroll
        for (int ks = 0; ks < 4; ks++) {
            unsigned ah[2][4], al[2][4];
#pragma unroll
            for (int mt = 0; mt < 2; mt++) {
                uint32_t base = sb + (uint32_t)((wm * 32 + mt * 16) * SROW + ks * 32) + a_off;
                ldsm4(ah[mt], base + AHI);
                ldsm4(al[mt], base + ALO);
            }
#pragma unroll
            for (int nt = 0; nt < 4; nt++) {
                unsigned bh[4], bl[4];
                uint32_t base = sb + (uint32_t)((wn * 64 + nt * 16) * SROW + ks * 32) + b_off;
                ldsm4(bh, base + BHI);
                ldsm4(bl, base + BLO);
#pragma unroll
                for (int mt = 0; mt < 2; mt++) {
#pragma unroll
                    for (int nn = 0; nn < 2; nn++) {
                        float* dd = d[mt][nt * 2 + nn];
                        mma_bf16(dd, ah[mt], bh[2 * nn], bh[2 * nn + 1]);
                        mma_bf16(dd, ah[mt], bl[2 * nn], bl[2 * nn + 1]);
                        mma_bf16(dd, al[mt], bh[2 * nn], bh[2 * nn + 1]);
                    }
                }
            }
        }
    }

    int g = lane >> 2, q = lane & 3;
#pragma unroll
    for (int mt = 0; mt < 2; mt++) {
        int r0 = m0 + wm * 32 + mt * 16 + g;
#pragma unroll
        for (int jq = 0; jq < 8; jq++) {
            int c = n0 + wn * 64 + jq * 8 + 2 * q;
            float* dd = d[mt][jq];
#pragma unroll
            for (int h = 0; h < 2; h++) {
                int m = r0 + h * 8;
                float v0 = dd[2 * h], v1 = dd[2 * h + 1];
                if constexpr (MODE == 2) {
                    size_t idx = (size_t)m * 256 + c;
                    *(float2*)(out + X_OFF + idx) = make_float2(v0, v1);
                    int trow = m >> 8;
                    if ((trow & 7) == 0) {  // fused c0 init
                        int b = trow >> 3, batch = m & 255;
                        size_t ci = ((size_t)b * 256 + batch) * 256 + c;
                        unsigned lp, hp = pack_hilo(v0, v1, lp);
                        *(unsigned*)(c_hi(0) + ci) = hp;
                        *(unsigned*)(c_lo(0) + ci) = lp;
                    }
                } else if constexpr (MODE == 3) {
                    int b = m >> 8, batch = m & 255;
                    int t = 8 * b + jv;
                    size_t xidx = (((size_t)t * 256) + batch) * 256 + c;
                    size_t ci = (size_t)m * 256 + c;
                    float2 dr = *(const float2*)(out + X_OFF + xidx);
                    float s0 = v0 + dr.x, s1 = v1 + dr.y;
                    unsigned lp, hp = pack_hilo(s0, s1, lp);
                    *(unsigned*)(c_hi(jv) + ci) = hp;
                    *(unsigned*)(c_lo(jv) + ci) = lp;
                } else {
                    int b = m >> 8, batch = m & 255;
                    int t = 8 * b + jv;
                    size_t xidx = (((size_t)t * 256) + batch) * 256 + c;
                    size_t ci = (size_t)m * 256 + c;
                    unsigned chp = *(const unsigned*)(c_hi(jv) + ci);
                    unsigned clp = *(const unsigned*)(c_lo(jv) + ci);
                    __nv_bfloat162 ch = *(__nv_bfloat162*)&chp;
                    __nv_bfloat162 cl = *(__nv_bfloat162*)&clp;
                    float xv0 = v0 + bf2f(__low2bfloat16(ch)) + bf2f(__low2bfloat16(cl));
                    float xv1 = v1 + bf2f(__high2bfloat16(ch)) + bf2f(__high2bfloat16(cl));
                    *(float2*)(out + X_OFF + xidx) = make_float2(xv0, xv1);
                    float2 mn = *(const float2*)(p4 + xidx);
                    float2 mx = *(const float2*)(p5 + xidx);
                    *(float2*)(out + SXMIN_OFF + xidx) =
                        make_float2(fmaxf(mn.x - xv0, 0.f), fmaxf(mn.y - xv1, 0.f));
                    *(float2*)(out + SXMAX_OFF + xidx) =
                        make_float2(fmaxf(xv0 - mx.x, 0.f), fmaxf(xv1 - mx.y, 0.f));
                    if (c == 254) out[Y_OFF + (size_t)t * 256 + batch] = xv1;
                }
            }
        }
    }
}

// ---------------- carry scan: s_{b+1} = s_b @ A^8 + c_{b,7}, 63 steps ----------------
struct ScanSmem {
    float A[256][128];
    ulonglong2 xs2[2][256];
    unsigned long long part[4][64][2][2];
};

__global__ void __launch_bounds__(256, 1) __cluster_dims__(2, 1, 1)
carry_scan_kernel(const float* __restrict__ x0) {
    extern __shared__ char smem_raw[];
    ScanSmem* S = reinterpret_cast<ScanSmem*>(smem_raw);
    int tid = threadIdx.x;
    unsigned rank = ctarank();
    int b0 = (int)(blockIdx.x >> 1) * 4;

    const float* A8 = g_P + 7 * 65536;
#pragma unroll
    for (int it = 0; it < 32; it++) {
        int idx4 = tid + it * 256;
        int jq = idx4 >> 5;
        int c4 = idx4 & 31;
        float4 v = *(const float4*)(A8 + (size_t)jq * 256 + rank * 128 + c4 * 4);
        *(float4*)(&S->A[jq][c4 * 4]) = v;
    }
    {
        int jq = tid;
        float a[4];
#pragma unroll
        for (int r = 0; r < 4; r++) {
            a[r] = x0[(b0 + r) * 256 + jq];
            __nv_bfloat16 h, l;
            split1(a[r], h, l);
            size_t si = (size_t)(b0 + r) * 256 + jq;
            g_u_hi[si] = h;
            g_u_lo[si] = l;
        }
        S->xs2[0][jq] = make_ulonglong2(pk2(a[0], a[1]), pk2(a[2], a[3]));
    }
    __syncthreads();

    const int jj = tid >> 6;
    const int cp = tid & 63;
    const int il = tid & 127;
    const int h  = tid >> 7;
    const int gcol = (int)rank * 128 + il;

    const __nv_bfloat16* c7h = c_hi(7);
    const __nv_bfloat16* c7l = c_lo(7);

    float pf_d0, pf_d1;
    {
        size_t ci = ((size_t)(b0 + 2 * h)) * 256 + gcol;
        pf_d0 = bf2f(c7h[ci]) + bf2f(c7l[ci]);
        pf_d1 = bf2f(c7h[ci + 256]) + bf2f(c7l[ci + 256]);
    }

    for (int b = 0; b < 63; b++) {
        int p = b & 1;
        unsigned long long a00 = 0, a01 = 0, a10 = 0, a11 = 0;
        const ulonglong2* xb = S->xs2[p];
        const float2* Arow = (const float2*)&S->A[jj * 64][0] + cp;
#pragma unroll 8
        for (int it = 0; it < 64; it++) {
            int jq = jj * 64 + it;
            float2 a = Arow[(size_t)it * 64];
            ulonglong2 xv = xb[jq];
            unsigned long long b0p = bcast2(a.x), b1p = bcast2(a.y);
            fma2(a00, b0p, xv.x);
            fma2(a01, b0p, xv.y);
            fma2(a10, b1p, xv.x);
            fma2(a11, b1p, xv.y);
        }
        S->part[jj][cp][0][0] = a00;
        S->part[jj][cp][0][1] = a01;
        S->part[jj][cp][1][0] = a10;
        S->part[jj][cp][1][1] = a11;
        __syncthreads();

        int cp2 = il >> 1, cip = il & 1;
        unsigned long long s = S->part[0][cp2][cip][h];
        add2(s, S->part[1][cp2][cip][h]);
        add2(s, S->part[2][cp2][cip][h]);
        add2(s, S->part[3][cp2][cip][h]);
        float2 sv = unpk(s);
        float v0 = sv.x + pf_d0;
        float v1 = sv.y + pf_d1;

        {
            size_t row0 = (size_t)(b + 1) * 256 + b0 + 2 * h;
            __nv_bfloat16 hh, ll;
            split1(v0, hh, ll);
            g_u_hi[row0 * 256 + gcol] = hh;
            g_u_lo[row0 * 256 + gcol] = ll;
            split1(v1, hh, ll);
            g_u_hi[(row0 + 1) * 256 + gcol] = hh;
            g_u_lo[(row0 + 1) * 256 + gcol] = ll;
        }

        unsigned long long xn = pk2(v0, v1);
        unsigned long long* dst =
            (h == 0) ? &S->xs2[p ^ 1][gcol].x : &S->xs2[p ^ 1][gcol].y;
        *dst = xn;
        unsigned laddr = smem_u32(dst);
        unsigned raddr;
        asm("mapa.shared::cluster.u32 %0, %1, %2;" : "=r"(raddr) : "r"(laddr), "r"(rank ^ 1u));
        asm volatile("st.shared::cluster.u64 [%0], %1;" :: "r"(raddr), "l"(xn) : "memory");

        int bn = (b < 62) ? b + 1 : 62;
        size_t cin = ((size_t)bn * 256 + b0 + 2 * h) * 256 + gcol;
        pf_d0 = bf2f(c7h[cin]) + bf2f(c7l[cin]);
        pf_d1 = bf2f(c7h[cin + 256]) + bf2f(c7l[cin + 256]);

        asm volatile("barrier.cluster.arrive.aligned;" ::: "memory");
        asm volatile("barrier.cluster.wait.aligned;" ::: "memory");
    }
}

// ---------------- launch ----------------
extern "C" void kernel_launch(void* const* d_in, const int* in_sizes, int n_in,
                              void* d_out, int out_size) {
    const float* x      = (const float*)d_in[0];
    const float* M_flow = (const float*)d_in[1];
    const float* DT     = (const float*)d_in[2];
    const float* D      = (const float*)d_in[3];
    const float* XMIN   = (const float*)d_in[4];
    const float* XMAX   = (const float*)d_in[5];
    const float* UMIN   = (const float*)d_in[6];
    const float* UMAX   = (const float*)d_in[7];
    const float* A_w    = (const float*)d_in[8];
    const float* A_sc   = (const float*)d_in[9];
    const float* B_W    = (const float*)d_in[10];
    const float* E_W    = (const float*)d_in[11];
    const float* hf1_W  = (const float*)d_in[12];
    const float* hf2_W  = (const float*)d_in[13];
    float* out = (float*)d_out;

    build_aeff_kernel<<<256, 256>>>(A_w, A_sc);
    pow_kernel<<<dim3(256, 1, 1), 256>>>(0, 0, 1);
    pow_kernel<<<dim3(256, 1, 2), 256>>>(1, 0, 2);
    pow_kernel<<<dim3(256, 1, 4), 256>>>(3, 0, 4);
    transp_kernel<<<dim3(8, 8, 8), dim3(32, 8)>>>();

    const int smem01 = 3 * 128 * SROW;  // 55296
    const int smemBF = 4 * 128 * SROW;  // 73728
    cudaFuncSetAttribute(gemm01_kernel<0>, cudaFuncAttributeMaxDynamicSharedMemorySize, smem01);
    cudaFuncSetAttribute(gemm01_kernel<1>, cudaFuncAttributeMaxDynamicSharedMemorySize, smem01);
    cudaFuncSetAttribute(gemm_bf_kernel<2>, cudaFuncAttributeMaxDynamicSharedMemorySize, smemBF);
    cudaFuncSetAttribute(gemm_bf_kernel<3>, cudaFuncAttributeMaxDynamicSharedMemorySize, smemBF);
    cudaFuncSetAttribute(gemm_bf_kernel<4>, cudaFuncAttributeMaxDynamicSharedMemorySize, smemBF);

    gemm01_kernel<0><<<dim3(4, 1024), 256, smem01>>>(M_flow, DT, hf1_W, nullptr, nullptr, out);
    gemm01_kernel<1><<<dim3(2, 1024), 256, smem01>>>(nullptr, nullptr, hf2_W, UMIN, UMAX, out);
    gemm_bf_kernel<2><<<dim3(2, 1024), 256, smemBF>>>(D, B_W, E_W, nullptr, nullptr, out, 0);

    for (int j = 1; j <= 7; j++)
        gemm_bf_kernel<3><<<dim3(2, 128), 256, smemBF>>>(nullptr, nullptr, nullptr, nullptr, nullptr, out, j);

    cudaFuncSetAttribute(carry_scan_kernel, cudaFuncAttributeMaxDynamicSharedMemorySize,
                         (int)sizeof(ScanSmem));
    carry_scan_kernel<<<128, 256, sizeof(ScanSmem)>>>(x);

    gemm_bf_kernel<4><<<dim3(2, 128, 8), 256, smemBF>>>(nullptr, nullptr, nullptr, XMIN, XMAX, out, 0);
}

// round 11
// speedup vs baseline: 1.3607x; 1.1188x over previous
#include <cuda_runtime.h>
#include <cuda_bf16.h>
#include <cuda_fp16.h>
#include <cstdint>
#include <cstddef>

// T=512, B=256, NX=256, NU=256, ND=128, NM=128, NDT=128, NH=512, M=T*B=131072
static constexpr size_t X_OFF     = 0;
static constexpr size_t Y_OFF     = 33554432;
static constexpr size_t SXMIN_OFF = 33685504;
static constexpr size_t SXMAX_OFF = 67239936;
static constexpr size_t SUMIN_OFF = 100794368;
static constexpr size_t SUMAX_OFF = 134348800;

// Powers: g_P[k][j*256+i] = (A_eff)^(k+1)[j][i]
__device__ float g_P[8 * 65536];
__device__ __half g_PT_hi[8 * 65536];  // g_PT[k][n*256+kk] = P_k[kk][n], fp16 hi/lo
__device__ __half g_PT_lo[8 * 65536];

// h: fp16 (mode0 out, mode1 in). Reused as c-scratch (fp16 pairs) after mode1.
__device__ __half g_h[(size_t)131072 * 512];
__device__ __half g_u[(size_t)131072 * 256];    // u fp16 single
__device__ __half g_s[16384 * 256];             // s states fp16 single

static constexpr size_t CSTRIDE = (size_t)16384 * 256;
__device__ __forceinline__ __half* c_hi(int j) {
    return g_h + (size_t)j * 2 * CSTRIDE;
}
__device__ __forceinline__ __half* c_lo(int j) {
    return g_h + (size_t)j * 2 * CSTRIDE + CSTRIDE;
}

// ---------------- scalar helpers ----------------
__device__ __forceinline__ unsigned long long pk2(float a, float b) {
    unsigned long long r;
    asm("mov.b64 %0, {%1, %2};" : "=l"(r) : "r"(__float_as_uint(a)), "r"(__float_as_uint(b)));
    return r;
}
__device__ __forceinline__ unsigned long long bcast2(float v) {
    unsigned long long r;
    unsigned u = __float_as_uint(v);
    asm("mov.b64 %0, {%1, %1};" : "=l"(r) : "r"(u));
    return r;
}
__device__ __forceinline__ void fma2(unsigned long long& d, unsigned long long a, unsigned long long b) {
    asm("fma.rn.f32x2 %0, %1, %2, %0;" : "+l"(d) : "l"(a), "l"(b));
}
__device__ __forceinline__ void add2(unsigned long long& d, unsigned long long a) {
    asm("add.rn.f32x2 %0, %0, %1;" : "+l"(d) : "l"(a));
}
__device__ __forceinline__ float2 unpk(unsigned long long v) {
    unsigned lo, hi;
    asm("mov.b64 {%0, %1}, %2;" : "=r"(lo), "=r"(hi) : "l"(v));
    return make_float2(__uint_as_float(lo), __uint_as_float(hi));
}
__device__ __forceinline__ unsigned smem_u32(const void* p) {
    unsigned r;
    asm("{ .reg .u64 t; cvta.to.shared.u64 t, %1; cvt.u32.u64 %0, t; }" : "=r"(r) : "l"(p));
    return r;
}
__device__ __forceinline__ unsigned ctarank() {
    unsigned r;
    asm("mov.u32 %0, %%cluster_ctarank;" : "=r"(r));
    return r;
}
__device__ __forceinline__ void ldsm4(unsigned* r, uint32_t addr) {
    asm volatile("ldmatrix.sync.aligned.m8n8.x4.shared.b16 {%0,%1,%2,%3}, [%4];"
                 : "=r"(r[0]), "=r"(r[1]), "=r"(r[2]), "=r"(r[3]) : "r"(addr));
}
__device__ __forceinline__ void mma_f16(float* d, const unsigned* a, unsigned b0, unsigned b1) {
    asm volatile(
        "mma.sync.aligned.m16n8k16.row.col.f32.f16.f16.f32 "
        "{%0,%1,%2,%3}, {%4,%5,%6,%7}, {%8,%9}, {%0,%1,%2,%3};"
        : "+f"(d[0]), "+f"(d[1]), "+f"(d[2]), "+f"(d[3])
        : "r"(a[0]), "r"(a[1]), "r"(a[2]), "r"(a[3]), "r"(b0), "r"(b1));
}
// 8 f32 -> fp16 hi/lo pair
__device__ __forceinline__ void cvt8h(const float* f, uint4& hi4, uint4& lo4) {
    unsigned h[4], l[4];
#pragma unroll
    for (int i = 0; i < 4; i++) {
        __half h0 = __float2half_rn(f[2 * i]);
        __half h1 = __float2half_rn(f[2 * i + 1]);
        __half l0 = __float2half_rn(f[2 * i] - __half2float(h0));
        __half l1 = __float2half_rn(f[2 * i + 1] - __half2float(h1));
        h[i] = (unsigned)__half_as_ushort(h0) | ((unsigned)__half_as_ushort(h1) << 16);
        l[i] = (unsigned)__half_as_ushort(l0) | ((unsigned)__half_as_ushort(l1) << 16);
    }
    hi4 = make_uint4(h[0], h[1], h[2], h[3]);
    lo4 = make_uint4(l[0], l[1], l[2], l[3]);
}
// 8 f32 -> fp16 hi only
__device__ __forceinline__ uint4 cvt8h_hi(const float* f) {
    unsigned h[4];
#pragma unroll
    for (int i = 0; i < 4; i++) {
        __half h0 = __float2half_rn(f[2 * i]);
        __half h1 = __float2half_rn(f[2 * i + 1]);
        h[i] = (unsigned)__half_as_ushort(h0) | ((unsigned)__half_as_ushort(h1) << 16);
    }
    return make_uint4(h[0], h[1], h[2], h[3]);
}
__device__ __forceinline__ void load8f(const float* src, float* f) {
    *(float4*)f = *(const float4*)src;
    *(float4*)(f + 4) = *(const float4*)(src + 4);
}
__device__ __forceinline__ unsigned pack_h16(float a, float b) {
    return (unsigned)__half_as_ushort(__float2half_rn(a)) |
           ((unsigned)__half_as_ushort(__float2half_rn(b)) << 16);
}
__device__ __forceinline__ unsigned pack_hilo16(float a, float b, unsigned& lo_out) {
    __half h0 = __float2half_rn(a), h1 = __float2half_rn(b);
    __half l0 = __float2half_rn(a - __half2float(h0));
    __half l1 = __float2half_rn(b - __half2float(h1));
    lo_out = (unsigned)__half_as_ushort(l0) | ((unsigned)__half_as_ushort(l1) << 16);
    return (unsigned)__half_as_ushort(h0) | ((unsigned)__half_as_ushort(h1) << 16);
}
__device__ __forceinline__ float h2f(__half v) { return __half2float(v); }

// ---------------- A_eff prep (writes g_P[0]) ----------------
__global__ void build_aeff_kernel(const float* __restrict__ Aw, const float* __restrict__ Asc) {
    int r = blockIdx.x, c = threadIdx.x;
    __shared__ float red[256];
    float w = Aw[r * 256 + c];
    red[c] = w;
    __syncthreads();
#pragma unroll
    for (int s = 128; s > 0; s >>= 1) {
        if (c < s) red[c] = fmaxf(red[c], red[c + s]);
        __syncthreads();
    }
    float mx = red[0];
    __syncthreads();
    float e = expf(w - mx);
    red[c] = e;
    __syncthreads();
#pragma unroll
    for (int s = 128; s > 0; s >>= 1) {
        if (c < s) red[c] += red[c + s];
        __syncthreads();
    }
    float p = e / red[0];
    float sg = 1.f / (1.f + expf(-Asc[r * 256 + c]));
    g_P[c * 256 + r] = (1.f - 0.1f * sg) * p;
}

// ---------------- matrix powers ----------------
__global__ void pow_kernel(int lsrc, int rfirst, int dstfirst) {
    int row = blockIdx.x, i = threadIdx.x, z = blockIdx.z;
    const float* L = g_P + (size_t)lsrc * 65536;
    const float* R = g_P + (size_t)(rfirst + z) * 65536;
    float* Cd = g_P + (size_t)(dstfirst + z) * 65536;
    __shared__ float Lrow[256];
    Lrow[i] = L[row * 256 + i];
    __syncthreads();
    float a0 = 0, a1 = 0, a2 = 0, a3 = 0;
#pragma unroll 8
    for (int m = 0; m < 256; m += 4) {
        a0 = fmaf(Lrow[m + 0], R[(m + 0) * 256 + i], a0);
        a1 = fmaf(Lrow[m + 1], R[(m + 1) * 256 + i], a1);
        a2 = fmaf(Lrow[m + 2], R[(m + 2) * 256 + i], a2);
        a3 = fmaf(Lrow[m + 3], R[(m + 3) * 256 + i], a3);
    }
    Cd[row * 256 + i] = (a0 + a1) + (a2 + a3);
}

// ---------------- transpose+split powers (fp16 hi/lo) ----------------
__global__ void transp_kernel() {
    int k = blockIdx.x;
    int kt = blockIdx.y * 32;
    int nt = blockIdx.z * 32;
    int tx = threadIdx.x, ty = threadIdx.y;
    __shared__ float tile[32][33];
    const float* P = g_P + (size_t)k * 65536;
#pragma unroll
    for (int r = 0; r < 4; r++) {
        int kk = kt + ty + r * 8;
        tile[ty + r * 8][tx] = P[kk * 256 + nt + tx];
    }
    __syncthreads();
#pragma unroll
    for (int r = 0; r < 4; r++) {
        int n = nt + ty + r * 8;
        float v = tile[tx][ty + r * 8];
        __half h = __float2half_rn(v);
        __half l = __float2half_rn(v - __half2float(h));
        size_t o = (size_t)k * 65536 + (size_t)n * 256 + kt + tx;
        g_PT_hi[o] = h;
        g_PT_lo[o] = l;
    }
}

static constexpr int SROW = 144;  // 64 elems * 2B + 16B pad

// ---------------- unified fp16 HMMA GEMM ----------------
// MODE 0 (2-term): A=concat(M_flow,DT) cvt, K=256, B=hf1 cvt-pair, N=512 -> g_h fp16 = relu
// MODE 1 (2-term): A=g_h copy, K=512, B=hf2 cvt-pair, N=256 -> g_u fp16 = relu, Su_min/max
// MODE 2 (2-term): A=g_u copy | D cvt, K=384, B=B_W|E_W cvt-pair -> drive->out X + c0 pair
// MODE 3 (3-term): A=c(j-1) pair copy, K=256, B=PT[0] pair copy -> c(j) = C + drive_t
// MODE 4 (2-term): A=g_s copy, K=256, B=PT[j] pair copy, j=blockIdx.z -> X,Sx,Y epilogue
template <int MODE>
__global__ void __launch_bounds__(256, 2)
gemm_f16_kernel(const float* __restrict__ pA0, const float* __restrict__ pA1,
                const float* __restrict__ pB0, const float* __restrict__ pB1,
                const float* __restrict__ p4, const float* __restrict__ p5,
                float* __restrict__ out, int jparam) {
    constexpr int K = (MODE == 0) ? 256 : (MODE == 1) ? 512 : (MODE == 2) ? 384 : 256;
    constexpr int NCH = K / 64;
    constexpr bool APAIR = (MODE == 3);
    constexpr uint32_t AHI = 0;
    constexpr uint32_t ALO = APAIR ? 18432u : 0u;          // only mode 3
    constexpr uint32_t BHI = APAIR ? 36864u : 18432u;
    constexpr uint32_t BLO = BHI + 18432u;

    extern __shared__ char smem[];
    uint32_t sb = smem_u32(smem);

    int tid = threadIdx.x;
    int lane = tid & 31;
    int wid = tid >> 5;
    int wm = wid & 3;
    int wn = wid >> 2;
    int m0 = blockIdx.y * 128;
    int n0 = blockIdx.x * 128;
    int jv = (MODE == 4) ? (int)blockIdx.z : jparam;

    const __half* PTh = nullptr;
    const __half* PTl = nullptr;
    if constexpr (MODE == 3) { PTh = g_PT_hi; PTl = g_PT_lo; }
    if constexpr (MODE == 4) {
        PTh = g_PT_hi + (size_t)jv * 65536;
        PTl = g_PT_lo + (size_t)jv * 65536;
    }

    uint32_t a_off = (uint32_t)((lane & 15) * SROW + ((lane >> 4) << 3) * 2);
    uint32_t b_off = (uint32_t)((((lane & 7) | ((lane >> 4) << 3))) * SROW +
                                (((lane >> 3) & 1) << 3) * 2);

    float d[2][8][4];
#pragma unroll
    for (int i = 0; i < 2; i++)
#pragma unroll
        for (int jq = 0; jq < 8; jq++)
#pragma unroll
            for (int kq = 0; kq < 4; kq++) d[i][jq][kq] = 0.f;

    for (int kc = 0; kc < NCH; kc++) {
        int k0 = kc * 64;
        __syncthreads();
        // ---- stage A ----
#pragma unroll
        for (int it = 0; it < 4; it++) {
            int g = it * 256 + tid;
            int row = g >> 3, c8 = g & 7;
            int k = k0 + c8 * 8;
            size_t m = (size_t)(m0 + row);
            uint32_t off = (uint32_t)(row * SROW + c8 * 16);
            if constexpr (MODE == 0) {
                const float* src = (k < 128) ? pA0 + m * 128 + k : pA1 + m * 128 + (k - 128);
                float f[8];
                load8f(src, f);
                *(uint4*)(smem + AHI + off) = cvt8h_hi(f);
            } else if constexpr (MODE == 1) {
                *(uint4*)(smem + AHI + off) = *(const uint4*)(g_h + m * 512 + k);
            } else if constexpr (MODE == 2) {
                if (k < 256) {
                    *(uint4*)(smem + AHI + off) = *(const uint4*)(g_u + m * 256 + k);
                } else {
                    float f[8];
                    load8f(pA1 + m * 128 + (k - 256), f);
                    *(uint4*)(smem + AHI + off) = cvt8h_hi(f);
                }
            } else if constexpr (MODE == 3) {
                size_t gi = m * 256 + k;
                *(uint4*)(smem + AHI + off) = *(const uint4*)(c_hi(jv - 1) + gi);
                *(uint4*)(smem + ALO + off) = *(const uint4*)(c_lo(jv - 1) + gi);
            } else {
                *(uint4*)(smem + AHI + off) = *(const uint4*)(g_s + m * 256 + k);
            }
        }
        // ---- stage B ----
#pragma unroll
        for (int it = 0; it < 4; it++) {
            int g = it * 256 + tid;
            int row = g >> 3, c8 = g & 7;
            int k = k0 + c8 * 8;
            size_t n = (size_t)(n0 + row);
            uint32_t off = (uint32_t)(row * SROW + c8 * 16);
            if constexpr (MODE <= 2) {
                const float* src;
                if constexpr (MODE == 0) src = pB0 + n * 256 + k;
                else if constexpr (MODE == 1) src = pB0 + n * 512 + k;
                else src = (k < 256) ? pB0 + n * 256 + k : pB1 + n * 128 + (k - 256);
                float f[8];
                load8f(src, f);
                uint4 hv, lv;
                cvt8h(f, hv, lv);
                *(uint4*)(smem + BHI + off) = hv;
                *(uint4*)(smem + BLO + off) = lv;
            } else {
                size_t bi = n * 256 + k;
                *(uint4*)(smem + BHI + off) = *(const uint4*)(PTh + bi);
                *(uint4*)(smem + BLO + off) = *(const uint4*)(PTl + bi);
            }
        }
        __syncthreads();

        // ---- MMA ----
#pragma unroll
        for (int ks = 0; ks < 4; ks++) {
            unsigned ah[2][4], al[2][4];
#pragma unroll
            for (int mt = 0; mt < 2; mt++) {
                uint32_t base = sb + (uint32_t)((wm * 32 + mt * 16) * SROW + ks * 32) + a_off;
                ldsm4(ah[mt], base + AHI);
                if constexpr (APAIR) ldsm4(al[mt], base + ALO);
            }
#pragma unroll
            for (int nt = 0; nt < 4; nt++) {
                unsigned bh[4], bl[4];
                uint32_t base = sb + (uint32_t)((wn * 64 + nt * 16) * SROW + ks * 32) + b_off;
                ldsm4(bh, base + BHI);
                ldsm4(bl, base + BLO);
#pragma unroll
                for (int mt = 0; mt < 2; mt++) {
#pragma unroll
                    for (int nn = 0; nn < 2; nn++) {
                        float* dd = d[mt][nt * 2 + nn];
                        mma_f16(dd, ah[mt], bh[2 * nn], bh[2 * nn + 1]);
                        mma_f16(dd, ah[mt], bl[2 * nn], bl[2 * nn + 1]);
                        if constexpr (APAIR) mma_f16(dd, al[mt], bh[2 * nn], bh[2 * nn + 1]);
                    }
                }
            }
        }
    }

    // ---- epilogue ----
    int g = lane >> 2, q = lane & 3;
#pragma unroll
    for (int mt = 0; mt < 2; mt++) {
        int r0 = m0 + wm * 32 + mt * 16 + g;
#pragma unroll
        for (int jq = 0; jq < 8; jq++) {
            int c = n0 + wn * 64 + jq * 8 + 2 * q;
            float* dd = d[mt][jq];
#pragma unroll
            for (int h = 0; h < 2; h++) {
                int m = r0 + h * 8;
                float v0 = dd[2 * h], v1 = dd[2 * h + 1];
                if constexpr (MODE == 0) {
                    size_t idx = (size_t)m * 512 + c;
                    *(unsigned*)(g_h + idx) = pack_h16(fmaxf(v0, 0.f), fmaxf(v1, 0.f));
                } else if constexpr (MODE == 1) {
                    float u0 = fmaxf(v0, 0.f), u1 = fmaxf(v1, 0.f);
                    size_t idx = (size_t)m * 256 + c;
                    *(unsigned*)(g_u + idx) = pack_h16(u0, u1);
                    float2 mn = *(const float2*)(p4 + idx);
                    float2 mx = *(const float2*)(p5 + idx);
                    *(float2*)(out + SUMIN_OFF + idx) =
                        make_float2(fmaxf(mn.x - u0, 0.f), fmaxf(mn.y - u1, 0.f));
                    *(float2*)(out + SUMAX_OFF + idx) =
                        make_float2(fmaxf(u0 - mx.x, 0.f), fmaxf(u1 - mx.y, 0.f));
                } else if constexpr (MODE == 2) {
                    size_t idx = (size_t)m * 256 + c;
                    *(float2*)(out + X_OFF + idx) = make_float2(v0, v1);
                    int trow = m >> 8;
                    if ((trow & 7) == 0) {  // fused c0 init
                        int b = trow >> 3, batch = m & 255;
                        size_t ci = ((size_t)b * 256 + batch) * 256 + c;
                        unsigned lp, hp = pack_hilo16(v0, v1, lp);
                        *(unsigned*)(c_hi(0) + ci) = hp;
                        *(unsigned*)(c_lo(0) + ci) = lp;
                    }
                } else if constexpr (MODE == 3) {
                    int b = m >> 8, batch = m & 255;
                    int t = 8 * b + jv;
                    size_t xidx = (((size_t)t * 256) + batch) * 256 + c;
                    size_t ci = (size_t)m * 256 + c;
                    float2 dr = *(const float2*)(out + X_OFF + xidx);
                    unsigned lp, hp = pack_hilo16(v0 + dr.x, v1 + dr.y, lp);
                    *(unsigned*)(c_hi(jv) + ci) = hp;
                    *(unsigned*)(c_lo(jv) + ci) = lp;
                } else {
                    int b = m >> 8, batch = m & 255;
                    int t = 8 * b + jv;
                    size_t xidx = (((size_t)t * 256) + batch) * 256 + c;
                    size_t ci = (size_t)m * 256 + c;
                    unsigned chp = *(const unsigned*)(c_hi(jv) + ci);
                    unsigned clp = *(const unsigned*)(c_lo(jv) + ci);
                    __half2 ch = *(__half2*)&chp;
                    __half2 cl = *(__half2*)&clp;
                    float xv0 = v0 + h2f(__low2half(ch)) + h2f(__low2half(cl));
                    float xv1 = v1 + h2f(__high2half(ch)) + h2f(__high2half(cl));
                    *(float2*)(out + X_OFF + xidx) = make_float2(xv0, xv1);
                    float2 mn = *(const float2*)(p4 + xidx);
                    float2 mx = *(const float2*)(p5 + xidx);
                    *(float2*)(out + SXMIN_OFF + xidx) =
                        make_float2(fmaxf(mn.x - xv0, 0.f), fmaxf(mn.y - xv1, 0.f));
                    *(float2*)(out + SXMAX_OFF + xidx) =
                        make_float2(fmaxf(xv0 - mx.x, 0.f), fmaxf(xv1 - mx.y, 0.f));
                    if (c == 254) out[Y_OFF + (size_t)t * 256 + batch] = xv1;
                }
            }
        }
    }
}

// ---------------- carry scan: s_{b+1} = s_b @ A^8 + c_{b,7}, 63 steps ----------------
struct ScanSmem {
    float A[256][128];
    ulonglong2 xs2[2][256];
    unsigned long long part[4][64][2][2];
};

__global__ void __launch_bounds__(256, 1) __cluster_dims__(2, 1, 1)
carry_scan_kernel(const float* __restrict__ x0) {
    extern __shared__ char smem_raw[];
    ScanSmem* S = reinterpret_cast<ScanSmem*>(smem_raw);
    int tid = threadIdx.x;
    unsigned rank = ctarank();
    int b0 = (int)(blockIdx.x >> 1) * 4;

    const float* A8 = g_P + 7 * 65536;
#pragma unroll
    for (int it = 0; it < 32; it++) {
        int idx4 = tid + it * 256;
        int jq = idx4 >> 5;
        int c4 = idx4 & 31;
        float4 v = *(const float4*)(A8 + (size_t)jq * 256 + rank * 128 + c4 * 4);
        *(float4*)(&S->A[jq][c4 * 4]) = v;
    }
    {
        int jq = tid;
        float a[4];
#pragma unroll
        for (int r = 0; r < 4; r++) {
            a[r] = x0[(b0 + r) * 256 + jq];
            g_s[(size_t)(b0 + r) * 256 + jq] = __float2half_rn(a[r]);
        }
        S->xs2[0][jq] = make_ulonglong2(pk2(a[0], a[1]), pk2(a[2], a[3]));
    }
    __syncthreads();

    const int jj = tid >> 6;
    const int cp = tid & 63;
    const int il = tid & 127;
    const int h  = tid >> 7;
    const int gcol = (int)rank * 128 + il;

    const __half* c7h = c_hi(7);
    const __half* c7l = c_lo(7);

    float pf_d0, pf_d1;
    {
        size_t ci = ((size_t)(b0 + 2 * h)) * 256 + gcol;
        pf_d0 = h2f(c7h[ci]) + h2f(c7l[ci]);
        pf_d1 = h2f(c7h[ci + 256]) + h2f(c7l[ci + 256]);
    }

    for (int b = 0; b < 63; b++) {
        int p = b & 1;
        unsigned long long a00 = 0, a01 = 0, a10 = 0, a11 = 0;
        const ulonglong2* xb = S->xs2[p];
        const float2* Arow = (const float2*)&S->A[jj * 64][0] + cp;
#pragma unroll 8
        for (int it = 0; it < 64; it++) {
            int jq = jj * 64 + it;
            float2 a = Arow[(size_t)it * 64];
            ulonglong2 xv = xb[jq];
            unsigned long long b0p = bcast2(a.x), b1p = bcast2(a.y);
            fma2(a00, b0p, xv.x);
            fma2(a01, b0p, xv.y);
            fma2(a10, b1p, xv.x);
            fma2(a11, b1p, xv.y);
        }
        S->part[jj][cp][0][0] = a00;
        S->part[jj][cp][0][1] = a01;
        S->part[jj][cp][1][0] = a10;
        S->part[jj][cp][1][1] = a11;
        __syncthreads();

        int cp2 = il >> 1, cip = il & 1;
        unsigned long long s = S->part[0][cp2][cip][h];
        add2(s, S->part[1][cp2][cip][h]);
        add2(s, S->part[2][cp2][cip][h]);
        add2(s, S->part[3][cp2][cip][h]);
        float2 sv = unpk(s);
        float v0 = sv.x + pf_d0;
        float v1 = sv.y + pf_d1;

        {
            size_t row0 = (size_t)(b + 1) * 256 + b0 + 2 * h;
            g_s[row0 * 256 + gcol] = __float2half_rn(v0);
            g_s[(row0 + 1) * 256 + gcol] = __float2half_rn(v1);
        }

        unsigned long long xn = pk2(v0, v1);
        unsigned long long* dst =
            (h == 0) ? &S->xs2[p ^ 1][gcol].x : &S->xs2[p ^ 1][gcol].y;
        *dst = xn;
        unsigned laddr = smem_u32(dst);
        unsigned raddr;
        asm("mapa.shared::cluster.u32 %0, %1, %2;" : "=r"(raddr) : "r"(laddr), "r"(rank ^ 1u));
        asm volatile("st.shared::cluster.u64 [%0], %1;" :: "r"(raddr), "l"(xn) : "memory");

        int bn = (b < 62) ? b + 1 : 62;
        size_t cin = ((size_t)bn * 256 + b0 + 2 * h) * 256 + gcol;
        pf_d0 = h2f(c7h[cin]) + h2f(c7l[cin]);
        pf_d1 = h2f(c7h[cin + 256]) + h2f(c7l[cin + 256]);

        asm volatile("barrier.cluster.arrive.aligned;" ::: "memory");
        asm volatile("barrier.cluster.wait.aligned;" ::: "memory");
    }
}

// ---------------- launch ----------------
extern "C" void kernel_launch(void* const* d_in, const int* in_sizes, int n_in,
                              void* d_out, int out_size) {
    const float* x      = (const float*)d_in[0];
    const float* M_flow = (const float*)d_in[1];
    const float* DT     = (const float*)d_in[2];
    const float* D      = (const float*)d_in[3];
    const float* XMIN   = (const float*)d_in[4];
    const float* XMAX   = (const float*)d_in[5];
    const float* UMIN   = (const float*)d_in[6];
    const float* UMAX   = (const float*)d_in[7];
    const float* A_w    = (const float*)d_in[8];
    const float* A_sc   = (const float*)d_in[9];
    const float* B_W    = (const float*)d_in[10];
    const float* E_W    = (const float*)d_in[11];
    const float* hf1_W  = (const float*)d_in[12];
    const float* hf2_W  = (const float*)d_in[13];
    float* out = (float*)d_out;

    build_aeff_kernel<<<256, 256>>>(A_w, A_sc);
    pow_kernel<<<dim3(256, 1, 1), 256>>>(0, 0, 1);
    pow_kernel<<<dim3(256, 1, 2), 256>>>(1, 0, 2);
    pow_kernel<<<dim3(256, 1, 4), 256>>>(3, 0, 4);
    transp_kernel<<<dim3(8, 8, 8), dim3(32, 8)>>>();

    const int smem2t = 3 * 128 * SROW;  // 55296 (2-term modes)
    const int smem3t = 4 * 128 * SROW;  // 73728 (mode 3)
    cudaFuncSetAttribute(gemm_f16_kernel<0>, cudaFuncAttributeMaxDynamicSharedMemorySize, smem2t);
    cudaFuncSetAttribute(gemm_f16_kernel<1>, cudaFuncAttributeMaxDynamicSharedMemorySize, smem2t);
    cudaFuncSetAttribute(gemm_f16_kernel<2>, cudaFuncAttributeMaxDynamicSharedMemorySize, smem2t);
    cudaFuncSetAttribute(gemm_f16_kernel<3>, cudaFuncAttributeMaxDynamicSharedMemorySize, smem3t);
    cudaFuncSetAttribute(gemm_f16_kernel<4>, cudaFuncAttributeMaxDynamicSharedMemorySize, smem2t);

    gemm_f16_kernel<0><<<dim3(4, 1024), 256, smem2t>>>(M_flow, DT, hf1_W, nullptr, nullptr, nullptr, out, 0);
    gemm_f16_kernel<1><<<dim3(2, 1024), 256, smem2t>>>(nullptr, nullptr, hf2_W, nullptr, UMIN, UMAX, out, 0);
    gemm_f16_kernel<2><<<dim3(2, 1024), 256, smem2t>>>(nullptr, D, B_W, E_W, nullptr, nullptr, out, 0);

    for (int j = 1; j <= 7; j++)
        gemm_f16_kernel<3><<<dim3(2, 128), 256, smem3t>>>(nullptr, nullptr, nullptr, nullptr, nullptr, nullptr, out, j);

    cudaFuncSetAttribute(carry_scan_kernel, cudaFuncAttributeMaxDynamicSharedMemorySize,
                         (int)sizeof(ScanSmem));
    carry_scan_kernel<<<128, 256, sizeof(ScanSmem)>>>(x);

    gemm_f16_kernel<4><<<dim3(2, 128, 8), 256, smem2t>>>(nullptr, nullptr, nullptr, nullptr, XMIN, XMAX, out, 0);
}

// round 12
// speedup vs baseline: 1.3906x; 1.0219x over previous
#include <cuda_runtime.h>
#include <cuda_bf16.h>
#include <cuda_fp16.h>
#include <cstdint>
#include <cstddef>

// T=512, B=256, NX=256, NU=256, ND=128, NM=128, NDT=128, NH=512, M=T*B=131072
static constexpr size_t X_OFF     = 0;
static constexpr size_t Y_OFF     = 33554432;
static constexpr size_t SXMIN_OFF = 33685504;
static constexpr size_t SXMAX_OFF = 67239936;
static constexpr size_t SUMIN_OFF = 100794368;
static constexpr size_t SUMAX_OFF = 134348800;

// Powers: g_P[k][j*256+i] = (A_eff)^(k+1)[j][i]
__device__ float g_P[8 * 65536];
__device__ __half g_PT_hi[8 * 65536];  // g_PT[k][n*256+kk] = P_k[kk][n]
__device__ __half g_PT_lo[8 * 65536];

// h: fp16 (mode0 out, mode1 in). Reused as c-scratch (fp16 pairs) after mode1.
__device__ __half g_h[(size_t)131072 * 512];
__device__ __half g_u[(size_t)131072 * 256];    // u fp16 single
__device__ __half g_s[16384 * 256];             // s states fp16 single

// pre-split weights (fp16 hi/lo)
__device__ __half g_w1_hi[512 * 256];
__device__ __half g_w1_lo[512 * 256];
__device__ __half g_w2_hi[256 * 512];
__device__ __half g_w2_lo[256 * 512];
__device__ __half g_be_hi[256 * 384];
__device__ __half g_be_lo[256 * 384];

static constexpr size_t CSTRIDE = (size_t)16384 * 256;
__device__ __forceinline__ __half* c_hi(int j) {
    return g_h + (size_t)j * 2 * CSTRIDE;
}
__device__ __forceinline__ __half* c_lo(int j) {
    return g_h + (size_t)j * 2 * CSTRIDE + CSTRIDE;
}

// ---------------- scalar helpers ----------------
__device__ __forceinline__ unsigned long long pk2(float a, float b) {
    unsigned long long r;
    asm("mov.b64 %0, {%1, %2};" : "=l"(r) : "r"(__float_as_uint(a)), "r"(__float_as_uint(b)));
    return r;
}
__device__ __forceinline__ unsigned long long bcast2(float v) {
    unsigned long long r;
    unsigned u = __float_as_uint(v);
    asm("mov.b64 %0, {%1, %1};" : "=l"(r) : "r"(u));
    return r;
}
__device__ __forceinline__ void fma2(unsigned long long& d, unsigned long long a, unsigned long long b) {
    asm("fma.rn.f32x2 %0, %1, %2, %0;" : "+l"(d) : "l"(a), "l"(b));
}
__device__ __forceinline__ void add2(unsigned long long& d, unsigned long long a) {
    asm("add.rn.f32x2 %0, %0, %1;" : "+l"(d) : "l"(a));
}
__device__ __forceinline__ float2 unpk(unsigned long long v) {
    unsigned lo, hi;
    asm("mov.b64 {%0, %1}, %2;" : "=r"(lo), "=r"(hi) : "l"(v));
    return make_float2(__uint_as_float(lo), __uint_as_float(hi));
}
__device__ __forceinline__ unsigned smem_u32(const void* p) {
    unsigned r;
    asm("{ .reg .u64 t; cvta.to.shared.u64 t, %1; cvt.u32.u64 %0, t; }" : "=r"(r) : "l"(p));
    return r;
}
__device__ __forceinline__ unsigned ctarank() {
    unsigned r;
    asm("mov.u32 %0, %%cluster_ctarank;" : "=r"(r));
    return r;
}
__device__ __forceinline__ void ldsm4(unsigned* r, uint32_t addr) {
    asm volatile("ldmatrix.sync.aligned.m8n8.x4.shared.b16 {%0,%1,%2,%3}, [%4];"
                 : "=r"(r[0]), "=r"(r[1]), "=r"(r[2]), "=r"(r[3]) : "r"(addr));
}
__device__ __forceinline__ void mma_f16(float* d, const unsigned* a, unsigned b0, unsigned b1) {
    asm volatile(
        "mma.sync.aligned.m16n8k16.row.col.f32.f16.f16.f32 "
        "{%0,%1,%2,%3}, {%4,%5,%6,%7}, {%8,%9}, {%0,%1,%2,%3};"
        : "+f"(d[0]), "+f"(d[1]), "+f"(d[2]), "+f"(d[3])
        : "r"(a[0]), "r"(a[1]), "r"(a[2]), "r"(a[3]), "r"(b0), "r"(b1));
}
// 8 f32 -> fp16 hi only
__device__ __forceinline__ uint4 cvt8h_hi(const float* f) {
    unsigned h[4];
#pragma unroll
    for (int i = 0; i < 4; i++) {
        __half h0 = __float2half_rn(f[2 * i]);
        __half h1 = __float2half_rn(f[2 * i + 1]);
        h[i] = (unsigned)__half_as_ushort(h0) | ((unsigned)__half_as_ushort(h1) << 16);
    }
    return make_uint4(h[0], h[1], h[2], h[3]);
}
__device__ __forceinline__ void load8f(const float* src, float* f) {
    *(float4*)f = *(const float4*)src;
    *(float4*)(f + 4) = *(const float4*)(src + 4);
}
__device__ __forceinline__ unsigned pack_h16(float a, float b) {
    return (unsigned)__half_as_ushort(__float2half_rn(a)) |
           ((unsigned)__half_as_ushort(__float2half_rn(b)) << 16);
}
__device__ __forceinline__ unsigned pack_hilo16(float a, float b, unsigned& lo_out) {
    __half h0 = __float2half_rn(a), h1 = __float2half_rn(b);
    __half l0 = __float2half_rn(a - __half2float(h0));
    __half l1 = __float2half_rn(b - __half2float(h1));
    lo_out = (unsigned)__half_as_ushort(l0) | ((unsigned)__half_as_ushort(l1) << 16);
    return (unsigned)__half_as_ushort(h0) | ((unsigned)__half_as_ushort(h1) << 16);
}
__device__ __forceinline__ float h2f(__half v) { return __half2float(v); }

// ---------------- weight pre-split (tiny) ----------------
__global__ void convert_w_kernel(const float* __restrict__ hf1, const float* __restrict__ hf2,
                                 const float* __restrict__ BW, const float* __restrict__ EW) {
    int id = blockIdx.x * 256 + threadIdx.x;  // 0..131071
    if (blockIdx.y == 0) {
        float v = hf1[id];
        __half h = __float2half_rn(v);
        g_w1_hi[id] = h;
        g_w1_lo[id] = __float2half_rn(v - __half2float(h));
    } else if (blockIdx.y == 1) {
        float v = hf2[id];
        __half h = __float2half_rn(v);
        g_w2_hi[id] = h;
        g_w2_lo[id] = __float2half_rn(v - __half2float(h));
    } else {
        if (id < 256 * 384) {
            int n = id / 384, k = id % 384;
            float v = (k < 256) ? BW[n * 256 + k] : EW[n * 128 + (k - 256)];
            __half h = __float2half_rn(v);
            g_be_hi[id] = h;
            g_be_lo[id] = __float2half_rn(v - __half2float(h));
        }
    }
}

// ---------------- A_eff prep (writes g_P[0]) ----------------
__global__ void build_aeff_kernel(const float* __restrict__ Aw, const float* __restrict__ Asc) {
    int r = blockIdx.x, c = threadIdx.x;
    __shared__ float red[256];
    float w = Aw[r * 256 + c];
    red[c] = w;
    __syncthreads();
#pragma unroll
    for (int s = 128; s > 0; s >>= 1) {
        if (c < s) red[c] = fmaxf(red[c], red[c + s]);
        __syncthreads();
    }
    float mx = red[0];
    __syncthreads();
    float e = expf(w - mx);
    red[c] = e;
    __syncthreads();
#pragma unroll
    for (int s = 128; s > 0; s >>= 1) {
        if (c < s) red[c] += red[c + s];
        __syncthreads();
    }
    float p = e / red[0];
    float sg = 1.f / (1.f + expf(-Asc[r * 256 + c]));
    g_P[c * 256 + r] = (1.f - 0.1f * sg) * p;
}

// ---------------- matrix powers ----------------
__global__ void pow_kernel(int lsrc, int rfirst, int dstfirst) {
    int row = blockIdx.x, i = threadIdx.x, z = blockIdx.z;
    const float* L = g_P + (size_t)lsrc * 65536;
    const float* R = g_P + (size_t)(rfirst + z) * 65536;
    float* Cd = g_P + (size_t)(dstfirst + z) * 65536;
    __shared__ float Lrow[256];
    Lrow[i] = L[row * 256 + i];
    __syncthreads();
    float a0 = 0, a1 = 0, a2 = 0, a3 = 0;
#pragma unroll 8
    for (int m = 0; m < 256; m += 4) {
        a0 = fmaf(Lrow[m + 0], R[(m + 0) * 256 + i], a0);
        a1 = fmaf(Lrow[m + 1], R[(m + 1) * 256 + i], a1);
        a2 = fmaf(Lrow[m + 2], R[(m + 2) * 256 + i], a2);
        a3 = fmaf(Lrow[m + 3], R[(m + 3) * 256 + i], a3);
    }
    Cd[row * 256 + i] = (a0 + a1) + (a2 + a3);
}

// ---------------- transpose+split powers (fp16 hi/lo) ----------------
__global__ void transp_kernel() {
    int k = blockIdx.x;
    int kt = blockIdx.y * 32;
    int nt = blockIdx.z * 32;
    int tx = threadIdx.x, ty = threadIdx.y;
    __shared__ float tile[32][33];
    const float* P = g_P + (size_t)k * 65536;
#pragma unroll
    for (int r = 0; r < 4; r++) {
        int kk = kt + ty + r * 8;
        tile[ty + r * 8][tx] = P[kk * 256 + nt + tx];
    }
    __syncthreads();
#pragma unroll
    for (int r = 0; r < 4; r++) {
        int n = nt + ty + r * 8;
        float v = tile[tx][ty + r * 8];
        __half h = __float2half_rn(v);
        __half l = __float2half_rn(v - __half2float(h));
        size_t o = (size_t)k * 65536 + (size_t)n * 256 + kt + tx;
        g_PT_hi[o] = h;
        g_PT_lo[o] = l;
    }
}

static constexpr int SROW = 144;  // 64 elems * 2B + 16B pad

// ---------------- unified fp16 HMMA GEMM ----------------
// MODE 0 (2-term): A=concat(M_flow,DT) cvt, K=256, B=w1 pair, N=512 -> g_h fp16 = relu
// MODE 1 (2-term): A=g_h copy, K=512, B=w2 pair, N=256 -> g_u fp16 = relu, Su_min/max
// MODE 2 (2-term): A=g_u copy | D cvt, K=384, B=be pair -> drive->out X + c0 pair
// MODE 3 (3-term): A=c(j-1) pair, K=256, B=PT[0] pair -> c(j) = C + drive_t
// MODE 4 (2-term): A=g_s copy, K=256, B=PT[j] pair, j=blockIdx.z -> X,Sx,Y epilogue
template <int MODE>
__global__ void __launch_bounds__(256, 2)
gemm_f16_kernel(const float* __restrict__ pA0, const float* __restrict__ pA1,
                const float* __restrict__ p4, const float* __restrict__ p5,
                float* __restrict__ out, int jparam) {
    constexpr int K = (MODE == 0) ? 256 : (MODE == 1) ? 512 : (MODE == 2) ? 384 : 256;
    constexpr int NCH = K / 64;
    constexpr bool APAIR = (MODE == 3);
    constexpr uint32_t AHI = 0;
    constexpr uint32_t ALO = APAIR ? 18432u : 0u;
    constexpr uint32_t BHI = APAIR ? 36864u : 18432u;
    constexpr uint32_t BLO = BHI + 18432u;

    extern __shared__ char smem[];
    uint32_t sb = smem_u32(smem);

    int tid = threadIdx.x;
    int lane = tid & 31;
    int wid = tid >> 5;
    int wm = wid & 3;
    int wn = wid >> 2;
    int m0 = blockIdx.y * 128;
    int n0 = blockIdx.x * 128;
    int jv = (MODE == 4) ? (int)blockIdx.z : jparam;

    // B pair pointers + stride
    const __half* Bh;
    const __half* Bl;
    int sbn;
    if constexpr (MODE == 0) { Bh = g_w1_hi; Bl = g_w1_lo; sbn = 256; }
    else if constexpr (MODE == 1) { Bh = g_w2_hi; Bl = g_w2_lo; sbn = 512; }
    else if constexpr (MODE == 2) { Bh = g_be_hi; Bl = g_be_lo; sbn = 384; }
    else if constexpr (MODE == 3) { Bh = g_PT_hi; Bl = g_PT_lo; sbn = 256; }
    else {
        Bh = g_PT_hi + (size_t)jv * 65536;
        Bl = g_PT_lo + (size_t)jv * 65536;
        sbn = 256;
    }

    uint32_t a_off = (uint32_t)((lane & 15) * SROW + ((lane >> 4) << 3) * 2);
    uint32_t b_off = (uint32_t)((((lane & 7) | ((lane >> 4) << 3))) * SROW +
                                (((lane >> 3) & 1) << 3) * 2);

    float d[2][8][4];
#pragma unroll
    for (int i = 0; i < 2; i++)
#pragma unroll
        for (int jq = 0; jq < 8; jq++)
#pragma unroll
            for (int kq = 0; kq < 4; kq++) d[i][jq][kq] = 0.f;

    for (int kc = 0; kc < NCH; kc++) {
        int k0 = kc * 64;
        __syncthreads();
        // ---- stage A ----
#pragma unroll
        for (int it = 0; it < 4; it++) {
            int g = it * 256 + tid;
            int row = g >> 3, c8 = g & 7;
            int k = k0 + c8 * 8;
            size_t m = (size_t)(m0 + row);
            uint32_t off = (uint32_t)(row * SROW + c8 * 16);
            if constexpr (MODE == 0) {
                const float* src = (k < 128) ? pA0 + m * 128 + k : pA1 + m * 128 + (k - 128);
                float f[8];
                load8f(src, f);
                *(uint4*)(smem + AHI + off) = cvt8h_hi(f);
            } else if constexpr (MODE == 1) {
                *(uint4*)(smem + AHI + off) = *(const uint4*)(g_h + m * 512 + k);
            } else if constexpr (MODE == 2) {
                if (k < 256) {
                    *(uint4*)(smem + AHI + off) = *(const uint4*)(g_u + m * 256 + k);
                } else {
                    float f[8];
                    load8f(pA1 + m * 128 + (k - 256), f);
                    *(uint4*)(smem + AHI + off) = cvt8h_hi(f);
                }
            } else if constexpr (MODE == 3) {
                size_t gi = m * 256 + k;
                *(uint4*)(smem + AHI + off) = *(const uint4*)(c_hi(jv - 1) + gi);
                *(uint4*)(smem + ALO + off) = *(const uint4*)(c_lo(jv - 1) + gi);
            } else {
                *(uint4*)(smem + AHI + off) = *(const uint4*)(g_s + m * 256 + k);
            }
        }
        // ---- stage B (pure pair copy) ----
#pragma unroll
        for (int it = 0; it < 4; it++) {
            int g = it * 256 + tid;
            int row = g >> 3, c8 = g & 7;
            int k = k0 + c8 * 8;
            size_t bi = (size_t)(n0 + row) * sbn + k;
            uint32_t off = (uint32_t)(row * SROW + c8 * 16);
            *(uint4*)(smem + BHI + off) = *(const uint4*)(Bh + bi);
            *(uint4*)(smem + BLO + off) = *(const uint4*)(Bl + bi);
        }
        __syncthreads();

        // ---- MMA ----
#pragma unroll
        for (int ks = 0; ks < 4; ks++) {
            unsigned ah[2][4], al[2][4];
#pragma unroll
            for (int mt = 0; mt < 2; mt++) {
                uint32_t base = sb + (uint32_t)((wm * 32 + mt * 16) * SROW + ks * 32) + a_off;
                ldsm4(ah[mt], base + AHI);
                if constexpr (APAIR) ldsm4(al[mt], base + ALO);
            }
#pragma unroll
            for (int nt = 0; nt < 4; nt++) {
                unsigned bh[4], bl[4];
                uint32_t base = sb + (uint32_t)((wn * 64 + nt * 16) * SROW + ks * 32) + b_off;
                ldsm4(bh, base + BHI);
                ldsm4(bl, base + BLO);
#pragma unroll
                for (int mt = 0; mt < 2; mt++) {
#pragma unroll
                    for (int nn = 0; nn < 2; nn++) {
                        float* dd = d[mt][nt * 2 + nn];
                        mma_f16(dd, ah[mt], bh[2 * nn], bh[2 * nn + 1]);
                        mma_f16(dd, ah[mt], bl[2 * nn], bl[2 * nn + 1]);
                        if constexpr (APAIR) mma_f16(dd, al[mt], bh[2 * nn], bh[2 * nn + 1]);
                    }
                }
            }
        }
    }

    // ---- epilogue ----
    int g = lane >> 2, q = lane & 3;
#pragma unroll
    for (int mt = 0; mt < 2; mt++) {
        int r0 = m0 + wm * 32 + mt * 16 + g;
#pragma unroll
        for (int jq = 0; jq < 8; jq++) {
            int c = n0 + wn * 64 + jq * 8 + 2 * q;
            float* dd = d[mt][jq];
#pragma unroll
            for (int h = 0; h < 2; h++) {
                int m = r0 + h * 8;
                float v0 = dd[2 * h], v1 = dd[2 * h + 1];
                if constexpr (MODE == 0) {
                    size_t idx = (size_t)m * 512 + c;
                    *(unsigned*)(g_h + idx) = pack_h16(fmaxf(v0, 0.f), fmaxf(v1, 0.f));
                } else if constexpr (MODE == 1) {
                    float u0 = fmaxf(v0, 0.f), u1 = fmaxf(v1, 0.f);
                    size_t idx = (size_t)m * 256 + c;
                    *(unsigned*)(g_u + idx) = pack_h16(u0, u1);
                    float2 mn = *(const float2*)(p4 + idx);
                    float2 mx = *(const float2*)(p5 + idx);
                    *(float2*)(out + SUMIN_OFF + idx) =
                        make_float2(fmaxf(mn.x - u0, 0.f), fmaxf(mn.y - u1, 0.f));
                    *(float2*)(out + SUMAX_OFF + idx) =
                        make_float2(fmaxf(u0 - mx.x, 0.f), fmaxf(u1 - mx.y, 0.f));
                } else if constexpr (MODE == 2) {
                    size_t idx = (size_t)m * 256 + c;
                    *(float2*)(out + X_OFF + idx) = make_float2(v0, v1);
                    int trow = m >> 8;
                    if ((trow & 7) == 0) {  // fused c0 init
                        int b = trow >> 3, batch = m & 255;
                        size_t ci = ((size_t)b * 256 + batch) * 256 + c;
                        unsigned lp, hp = pack_hilo16(v0, v1, lp);
                        *(unsigned*)(c_hi(0) + ci) = hp;
                        *(unsigned*)(c_lo(0) + ci) = lp;
                    }
                } else if constexpr (MODE == 3) {
                    int b = m >> 8, batch = m & 255;
                    int t = 8 * b + jv;
                    size_t xidx = (((size_t)t * 256) + batch) * 256 + c;
                    size_t ci = (size_t)m * 256 + c;
                    float2 dr = *(const float2*)(out + X_OFF + xidx);
                    unsigned lp, hp = pack_hilo16(v0 + dr.x, v1 + dr.y, lp);
                    *(unsigned*)(c_hi(jv) + ci) = hp;
                    *(unsigned*)(c_lo(jv) + ci) = lp;
                } else {
                    int b = m >> 8, batch = m & 255;
                    int t = 8 * b + jv;
                    size_t xidx = (((size_t)t * 256) + batch) * 256 + c;
                    size_t ci = (size_t)m * 256 + c;
                    unsigned chp = *(const unsigned*)(c_hi(jv) + ci);
                    unsigned clp = *(const unsigned*)(c_lo(jv) + ci);
                    __half2 ch = *(__half2*)&chp;
                    __half2 cl = *(__half2*)&clp;
                    float xv0 = v0 + h2f(__low2half(ch)) + h2f(__low2half(cl));
                    float xv1 = v1 + h2f(__high2half(ch)) + h2f(__high2half(cl));
                    *(float2*)(out + X_OFF + xidx) = make_float2(xv0, xv1);
                    float2 mn = *(const float2*)(p4 + xidx);
                    float2 mx = *(const float2*)(p5 + xidx);
                    *(float2*)(out + SXMIN_OFF + xidx) =
                        make_float2(fmaxf(mn.x - xv0, 0.f), fmaxf(mn.y - xv1, 0.f));
                    *(float2*)(out + SXMAX_OFF + xidx) =
                        make_float2(fmaxf(xv0 - mx.x, 0.f), fmaxf(xv1 - mx.y, 0.f));
                    if (c == 254) out[Y_OFF + (size_t)t * 256 + batch] = xv1;
                }
            }
        }
    }
}

// ---------------- carry scan: s_{b+1} = s_b @ A^8 + c_{b,7}, 63 steps ----------------
// mbarrier-based cluster exchange (peer arrives release; local waits acquire).
struct ScanSmem {
    float A[256][128];
    ulonglong2 xs2[2][256];
    unsigned long long part[4][64][2][2];
    unsigned long long mbar;
};

__global__ void __launch_bounds__(256, 1) __cluster_dims__(2, 1, 1)
carry_scan_kernel(const float* __restrict__ x0) {
    extern __shared__ char smem_raw[];
    ScanSmem* S = reinterpret_cast<ScanSmem*>(smem_raw);
    int tid = threadIdx.x;
    unsigned rank = ctarank();
    int b0 = (int)(blockIdx.x >> 1) * 4;

    const float* A8 = g_P + 7 * 65536;
#pragma unroll
    for (int it = 0; it < 32; it++) {
        int idx4 = tid + it * 256;
        int jq = idx4 >> 5;
        int c4 = idx4 & 31;
        float4 v = *(const float4*)(A8 + (size_t)jq * 256 + rank * 128 + c4 * 4);
        *(float4*)(&S->A[jq][c4 * 4]) = v;
    }
    {
        int jq = tid;
        float a[4];
#pragma unroll
        for (int r = 0; r < 4; r++) {
            a[r] = x0[(b0 + r) * 256 + jq];
            g_s[(size_t)(b0 + r) * 256 + jq] = __float2half_rn(a[r]);
        }
        S->xs2[0][jq] = make_ulonglong2(pk2(a[0], a[1]), pk2(a[2], a[3]));
    }
    uint32_t mbar_addr = smem_u32(&S->mbar);
    if (tid == 0) {
        asm volatile("mbarrier.init.shared.b64 [%0], %1;" :: "r"(mbar_addr), "r"(256u) : "memory");
    }
    __syncthreads();
    // ensure peer's mbarrier is initialized before any arrival lands on it
    asm volatile("barrier.cluster.arrive.aligned;" ::: "memory");
    asm volatile("barrier.cluster.wait.aligned;" ::: "memory");

    uint32_t peer_mbar;
    asm("mapa.shared::cluster.u32 %0, %1, %2;" : "=r"(peer_mbar) : "r"(mbar_addr), "r"(rank ^ 1u));

    const int jj = tid >> 6;
    const int cp = tid & 63;
    const int il = tid & 127;
    const int h  = tid >> 7;
    const int gcol = (int)rank * 128 + il;

    const __half* c7h = c_hi(7);
    const __half* c7l = c_lo(7);

    float pf_d0, pf_d1;
    {
        size_t ci = ((size_t)(b0 + 2 * h)) * 256 + gcol;
        pf_d0 = h2f(c7h[ci]) + h2f(c7l[ci]);
        pf_d1 = h2f(c7h[ci + 256]) + h2f(c7l[ci + 256]);
    }

    for (int b = 0; b < 63; b++) {
        int p = b & 1;
        unsigned long long a00 = 0, a01 = 0, a10 = 0, a11 = 0;
        const ulonglong2* xb = S->xs2[p];
        const float2* Arow = (const float2*)&S->A[jj * 64][0] + cp;
#pragma unroll 8
        for (int it = 0; it < 64; it++) {
            int jq = jj * 64 + it;
            float2 a = Arow[(size_t)it * 64];
            ulonglong2 xv = xb[jq];
            unsigned long long b0p = bcast2(a.x), b1p = bcast2(a.y);
            fma2(a00, b0p, xv.x);
            fma2(a01, b0p, xv.y);
            fma2(a10, b1p, xv.x);
            fma2(a11, b1p, xv.y);
        }
        S->part[jj][cp][0][0] = a00;
        S->part[jj][cp][0][1] = a01;
        S->part[jj][cp][1][0] = a10;
        S->part[jj][cp][1][1] = a11;
        __syncthreads();

        int cp2 = il >> 1, cip = il & 1;
        unsigned long long s = S->part[0][cp2][cip][h];
        add2(s, S->part[1][cp2][cip][h]);
        add2(s, S->part[2][cp2][cip][h]);
        add2(s, S->part[3][cp2][cip][h]);
        float2 sv = unpk(s);
        float v0 = sv.x + pf_d0;
        float v1 = sv.y + pf_d1;

        {
            size_t row0 = (size_t)(b + 1) * 256 + b0 + 2 * h;
            g_s[row0 * 256 + gcol] = __float2half_rn(v0);
            g_s[(row0 + 1) * 256 + gcol] = __float2half_rn(v1);
        }

        unsigned long long xn = pk2(v0, v1);
        unsigned long long* dst =
            (h == 0) ? &S->xs2[p ^ 1][gcol].x : &S->xs2[p ^ 1][gcol].y;
        *dst = xn;
        unsigned laddr = smem_u32(dst);
        unsigned raddr;
        asm("mapa.shared::cluster.u32 %0, %1, %2;" : "=r"(raddr) : "r"(laddr), "r"(rank ^ 1u));
        asm volatile("st.shared::cluster.u64 [%0], %1;" :: "r"(raddr), "l"(xn) : "memory");
        // release-arrive on peer's barrier (orders the peer-visible store above)
        asm volatile("mbarrier.arrive.release.cluster.shared::cluster.b64 _, [%0];"
                     :: "r"(peer_mbar) : "memory");

        int bn = (b < 62) ? b + 1 : 62;
        size_t cin = ((size_t)bn * 256 + b0 + 2 * h) * 256 + gcol;
        pf_d0 = h2f(c7h[cin]) + h2f(c7l[cin]);
        pf_d1 = h2f(c7h[cin + 256]) + h2f(c7l[cin + 256]);

        __syncthreads();  // local xs2 writes visible to local threads
        // wait for peer's 256 arrivals (phase parity = b&1)
        {
            uint32_t done;
            asm volatile(
                "{\n\t.reg .pred pp;\n\t"
                "mbarrier.try_wait.parity.acquire.cluster.shared::cta.b64 pp, [%1], %2;\n\t"
                "selp.b32 %0, 1, 0, pp;\n\t}"
                : "=r"(done) : "r"(mbar_addr), "r"((uint32_t)(b & 1)) : "memory");
            if (!done) {
                asm volatile(
                    "{\n\t.reg .pred P1;\n\tWL_%=:\n\t"
                    "mbarrier.try_wait.parity.acquire.cluster.shared::cta.b64 P1, [%0], %1, 0x989680;\n\t"
                    "@P1 bra.uni WD_%=;\n\tbra.uni WL_%=;\n\tWD_%=:\n\t}"
                    :: "r"(mbar_addr), "r"((uint32_t)(b & 1)) : "memory");
            }
        }
    }
}

// ---------------- launch ----------------
extern "C" void kernel_launch(void* const* d_in, const int* in_sizes, int n_in,
                              void* d_out, int out_size) {
    const float* x      = (const float*)d_in[0];
    const float* M_flow = (const float*)d_in[1];
    const float* DT     = (const float*)d_in[2];
    const float* D      = (const float*)d_in[3];
    const float* XMIN   = (const float*)d_in[4];
    const float* XMAX   = (const float*)d_in[5];
    const float* UMIN   = (const float*)d_in[6];
    const float* UMAX   = (const float*)d_in[7];
    const float* A_w    = (const float*)d_in[8];
    const float* A_sc   = (const float*)d_in[9];
    const float* B_W    = (const float*)d_in[10];
    const float* E_W    = (const float*)d_in[11];
    const float* hf1_W  = (const float*)d_in[12];
    const float* hf2_W  = (const float*)d_in[13];
    float* out = (float*)d_out;

    const int smem2t = 3 * 128 * SROW;  // 55296
    const int smem3t = 4 * 128 * SROW;  // 73728
    cudaFuncSetAttribute(gemm_f16_kernel<0>, cudaFuncAttributeMaxDynamicSharedMemorySize, smem2t);
    cudaFuncSetAttribute(gemm_f16_kernel<1>, cudaFuncAttributeMaxDynamicSharedMemorySize, smem2t);
    cudaFuncSetAttribute(gemm_f16_kernel<2>, cudaFuncAttributeMaxDynamicSharedMemorySize, smem2t);
    cudaFuncSetAttribute(gemm_f16_kernel<3>, cudaFuncAttributeMaxDynamicSharedMemorySize, smem3t);
    cudaFuncSetAttribute(gemm_f16_kernel<4>, cudaFuncAttributeMaxDynamicSharedMemorySize, smem2t);
    cudaFuncSetAttribute(carry_scan_kernel, cudaFuncAttributeMaxDynamicSharedMemorySize,
                         (int)sizeof(ScanSmem));

    // launch order arranged so index 3 = mode-1 GEMM (ncu capture target)
    convert_w_kernel<<<dim3(512, 3), 256>>>(hf1_W, hf2_W, B_W, E_W);               // 0
    build_aeff_kernel<<<256, 256>>>(A_w, A_sc);                                     // 1
    gemm_f16_kernel<0><<<dim3(4, 1024), 256, smem2t>>>(M_flow, DT, nullptr, nullptr, out, 0);  // 2
    gemm_f16_kernel<1><<<dim3(2, 1024), 256, smem2t>>>(nullptr, nullptr, UMIN, UMAX, out, 0);  // 3
    pow_kernel<<<dim3(256, 1, 1), 256>>>(0, 0, 1);                                  // 4
    pow_kernel<<<dim3(256, 1, 2), 256>>>(1, 0, 2);                                  // 5
    pow_kernel<<<dim3(256, 1, 4), 256>>>(3, 0, 4);                                  // 6
    transp_kernel<<<dim3(8, 8, 8), dim3(32, 8)>>>();                                // 7
    gemm_f16_kernel<2><<<dim3(2, 1024), 256, smem2t>>>(nullptr, D, nullptr, nullptr, out, 0);  // 8

    for (int j = 1; j <= 7; j++)
        gemm_f16_kernel<3><<<dim3(2, 128), 256, smem3t>>>(nullptr, nullptr, nullptr, nullptr, out, j);

    carry_scan_kernel<<<128, 256, sizeof(ScanSmem)>>>(x);

    gemm_f16_kernel<4><<<dim3(2, 128, 8), 256, smem2t>>>(nullptr, nullptr, XMIN, XMAX, out, 0);
}